// round 3
// baseline (speedup 1.0000x reference)
#include <cuda_runtime.h>
#include <math.h>

#define BATCH  1024
#define SEQN   128
#define DMODEL 256
#define NROWS  (BATCH*SEQN)            // 131072
#define ELEMS  (BATCH*SEQN*DMODEL)     // 33554432
#define SST    132                     // padded smem row stride (floats)

// ---------------- scratch (static device allocations; allowed) ----------------
__device__ float g_KV[ELEMS];
__device__ float g_Q [ELEMS];
__device__ float g_K [ELEMS];
__device__ float g_V [ELEMS];
__device__ float g_AO[ELEMS];
__device__ float g_FC[ELEMS];
__device__ float g_SA[ELEMS];
__device__ float g_H1[ELEMS];
__device__ float g_KC[ELEMS];
__device__ float g_KH[ELEMS];
__device__ float g_VH[ELEMS];
__device__ float g_QH[BATCH*DMODEL];
__device__ unsigned char g_mask8[NROWS];
__device__ int g_mask_mode;

// ---------------- mask dtype detection + normalization ----------------
__global__ void detect_mask_kernel(const void* mask) {
    if (threadIdx.x == 0 && blockIdx.x == 0) {
        const unsigned* p = (const unsigned*)mask;
        int mode = 1;  // default int32
        for (int i = 0; i < 1024; i++) {
            unsigned v = p[i];
            if (v == 0x3F800000u) { mode = 2; break; }  // float32 1.0f
            if (v > 1u) { mode = 0; break; }            // packed uint8 bools
        }
        g_mask_mode = mode;
    }
}

__global__ __launch_bounds__(256) void norm_mask_kernel(const void* mask) {
    int i = blockIdx.x * 256 + threadIdx.x;
    if (i >= NROWS) return;
    int mode = g_mask_mode;
    unsigned char m;
    if (mode == 0)      m = (((const unsigned char*)mask)[i] != 0);
    else if (mode == 1) m = (((const int*)mask)[i] != 0);
    else                m = (((const float*)mask)[i] != 0.f);
    g_mask8[i] = m;
}

// ---------------- concat([seq, seq_t], -1) -> KV ----------------
__global__ __launch_bounds__(256) void concat_kv_kernel(
    const float* __restrict__ seq, const float* __restrict__ seqt)
{
    long i4 = (long)blockIdx.x * 256 + threadIdx.x;   // float4 index
    if (i4 >= (long)ELEMS / 4) return;
    long row = i4 >> 6;            // 64 float4 per 256-float row
    int  c4  = (int)(i4 & 63);
    float4 v;
    if (c4 < 32) v = ((const float4*)(seq  + row * 128))[c4];
    else         v = ((const float4*)(seqt + row * 128))[c4 - 32];
    ((float4*)(g_KV + row * 256))[c4] = v;
}

// ---------------- generic fp32 GEMM: C = concat(A1,A2) @ W (+bias)(+res)(relu) ----------------
__global__ __launch_bounds__(256) void gemm_kernel(
    const float* __restrict__ A1, int K1, int lda1,
    const float* __restrict__ A2, int lda2,
    const float* __restrict__ W, int Ktot, int Ncols,
    const float* __restrict__ bias,
    const float* __restrict__ res,
    int relu,
    float* __restrict__ C)
{
    __shared__ float As[8][SST];   // [k][m] transposed
    __shared__ float Bs[8][128];   // [k][n]
    const int tid = threadIdx.x;
    const int tx = tid & 15, ty = tid >> 4;
    const long m0 = (long)blockIdx.y * 128;
    const int  n0 = blockIdx.x * 128;
    const int am = tid >> 1;
    const int ak = (tid & 1) * 4;
    const int bk = tid >> 5;
    const int bn = (tid & 31) * 4;

    float acc[8][8];
#pragma unroll
    for (int i = 0; i < 8; i++)
#pragma unroll
        for (int j = 0; j < 8; j++) acc[i][j] = 0.f;

    for (int k0 = 0; k0 < Ktot; k0 += 8) {
        int kg = k0 + ak;
        const float* ap = (kg < K1) ? (A1 + (m0 + am) * (long)lda1 + kg)
                                    : (A2 + (m0 + am) * (long)lda2 + (kg - K1));
        float4 av = *(const float4*)ap;
        As[ak + 0][am] = av.x; As[ak + 1][am] = av.y;
        As[ak + 2][am] = av.z; As[ak + 3][am] = av.w;
        *(float4*)&Bs[bk][bn] = *(const float4*)(W + (long)(k0 + bk) * Ncols + n0 + bn);
        __syncthreads();
#pragma unroll
        for (int k = 0; k < 8; k++) {
            float a[8], b[8];
#pragma unroll
            for (int i = 0; i < 8; i++) a[i] = As[k][ty * 8 + i];
#pragma unroll
            for (int j = 0; j < 8; j++) b[j] = Bs[k][tx * 8 + j];
#pragma unroll
            for (int i = 0; i < 8; i++)
#pragma unroll
                for (int j = 0; j < 8; j++)
                    acc[i][j] = fmaf(a[i], b[j], acc[i][j]);
        }
        __syncthreads();
    }

#pragma unroll
    for (int i = 0; i < 8; i++) {
        long m = m0 + ty * 8 + i;
        float vv[8];
#pragma unroll
        for (int j = 0; j < 8; j++) vv[j] = acc[i][j];
        if (bias) {
#pragma unroll
            for (int j = 0; j < 8; j++) vv[j] += bias[n0 + tx * 8 + j];
        }
        if (res) {
            float4 r0 = *(const float4*)(res + m * Ncols + n0 + tx * 8);
            float4 r1 = *(const float4*)(res + m * Ncols + n0 + tx * 8 + 4);
            vv[0] += r0.x; vv[1] += r0.y; vv[2] += r0.z; vv[3] += r0.w;
            vv[4] += r1.x; vv[5] += r1.y; vv[6] += r1.z; vv[7] += r1.w;
        }
        if (relu) {
#pragma unroll
            for (int j = 0; j < 8; j++) vv[j] = fmaxf(vv[j], 0.f);
        }
        *(float4*)(C + m * Ncols + n0 + tx * 8)     = make_float4(vv[0], vv[1], vv[2], vv[3]);
        *(float4*)(C + m * Ncols + n0 + tx * 8 + 4) = make_float4(vv[4], vv[5], vv[6], vv[7]);
    }
}

// ---------------- self-attention: one CTA per (head, batch) ----------------
__global__ __launch_bounds__(256) void sa_attn_kernel(
    const float* __restrict__ Q, const float* __restrict__ K, const float* __restrict__ V,
    const unsigned char* __restrict__ mask, float* __restrict__ O)
{
    extern __shared__ float sm[];
    float* Qt = sm;                  // [128][SST]
    float* Kt = sm + 128 * SST;      // [128][SST]
    float* Pt = sm + 2 * 128 * SST;  // [128][SST]  scores stored [k][q]
    __shared__ unsigned char smask[128];

    const int h = blockIdx.x, b = blockIdx.y;
    const int tid = threadIdx.x;
    const float* Qp = Q + ((long)b * SEQN) * DMODEL + h * 128;
    const float* Kp = K + ((long)b * SEQN) * DMODEL + h * 128;
    const float* Vp = V + ((long)b * SEQN) * DMODEL + h * 128;

    if (tid < 128) smask[tid] = mask[(long)b * SEQN + tid];
    for (int idx = tid; idx < 128 * 32; idx += 256) {
        int r = idx >> 5;
        int c = (idx & 31) << 2;
        float4 qv = *(const float4*)(Qp + (long)r * DMODEL + c);
        Qt[(c + 0) * SST + r] = qv.x; Qt[(c + 1) * SST + r] = qv.y;
        Qt[(c + 2) * SST + r] = qv.z; Qt[(c + 3) * SST + r] = qv.w;
        float4 kv = *(const float4*)(Kp + (long)r * DMODEL + c);
        Kt[(c + 0) * SST + r] = kv.x; Kt[(c + 1) * SST + r] = kv.y;
        Kt[(c + 2) * SST + r] = kv.z; Kt[(c + 3) * SST + r] = kv.w;
    }
    __syncthreads();

    const int tx = tid & 15, ty = tid >> 4;
    float acc[8][8];
#pragma unroll
    for (int i = 0; i < 8; i++)
#pragma unroll
        for (int j = 0; j < 8; j++) acc[i][j] = 0.f;
    for (int k = 0; k < 128; k++) {
        float a[8], bb[8];
#pragma unroll
        for (int i = 0; i < 8; i++) a[i]  = Qt[k * SST + ty * 8 + i];
#pragma unroll
        for (int j = 0; j < 8; j++) bb[j] = Kt[k * SST + tx * 8 + j];
#pragma unroll
        for (int i = 0; i < 8; i++)
#pragma unroll
            for (int j = 0; j < 8; j++)
                acc[i][j] = fmaf(a[i], bb[j], acc[i][j]);
    }
    // store transposed: Pt[key][query]
#pragma unroll
    for (int i = 0; i < 8; i++)
#pragma unroll
        for (int j = 0; j < 8; j++)
            Pt[(tx * 8 + j) * SST + ty * 8 + i] = acc[i][j];
    __syncthreads();

    // overlap: load V into Qt while doing softmax on Pt
    for (int idx = tid; idx < 128 * 32; idx += 256) {
        int r = idx >> 5;
        int c = (idx & 31) << 2;
        *(float4*)&Qt[r * SST + c] = *(const float4*)(Vp + (long)r * DMODEL + c);
    }
    const float invs = 0.0883883476483184f;  // 1/sqrt(128)
    const int warp = tid >> 5, lane = tid & 31;
    for (int r = warp; r < 128; r += 8) {     // r = query row
        float vv[4];
        float mx = -1e30f;
#pragma unroll
        for (int q = 0; q < 4; q++) {
            int c = lane + q * 32;            // key index
            float s = Pt[c * SST + r] * invs;
            if (smask[c]) s = -1e10f;
            vv[q] = s; mx = fmaxf(mx, s);
        }
#pragma unroll
        for (int o = 16; o > 0; o >>= 1) mx = fmaxf(mx, __shfl_xor_sync(0xffffffffu, mx, o));
        float sum = 0.f;
#pragma unroll
        for (int q = 0; q < 4; q++) { vv[q] = expf(vv[q] - mx); sum += vv[q]; }
#pragma unroll
        for (int o = 16; o > 0; o >>= 1) sum += __shfl_xor_sync(0xffffffffu, sum, o);
        float rs = 1.f / sum;
#pragma unroll
        for (int q = 0; q < 4; q++) Pt[(lane + q * 32) * SST + r] = vv[q] * rs;
    }
    __syncthreads();

    // O = P @ V
    float oc[8][8];
#pragma unroll
    for (int i = 0; i < 8; i++)
#pragma unroll
        for (int j = 0; j < 8; j++) oc[i][j] = 0.f;
    for (int k = 0; k < 128; k++) {
        float a[8], bb[8];
#pragma unroll
        for (int i = 0; i < 8; i++) a[i]  = Pt[k * SST + ty * 8 + i];
#pragma unroll
        for (int j = 0; j < 8; j++) bb[j] = Qt[k * SST + tx * 8 + j];
#pragma unroll
        for (int i = 0; i < 8; i++)
#pragma unroll
            for (int j = 0; j < 8; j++)
                oc[i][j] = fmaf(a[i], bb[j], oc[i][j]);
    }
    float* Op = O + ((long)b * SEQN) * DMODEL + h * 128;
#pragma unroll
    for (int i = 0; i < 8; i++) {
        *(float4*)(Op + (long)(ty * 8 + i) * DMODEL + tx * 8)     = make_float4(oc[i][0], oc[i][1], oc[i][2], oc[i][3]);
        *(float4*)(Op + (long)(ty * 8 + i) * DMODEL + tx * 8 + 4) = make_float4(oc[i][4], oc[i][5], oc[i][6], oc[i][7]);
    }
}

// ---------------- LayerNorm over 256, warp per row ----------------
__global__ __launch_bounds__(256) void ln_kernel(
    const float* __restrict__ X, const float* __restrict__ gw,
    const float* __restrict__ bw, float* __restrict__ Y)
{
    long row = (long)blockIdx.x * 8 + (threadIdx.x >> 5);
    int lane = threadIdx.x & 31;
    const float* xp = X + row * 256 + lane * 8;
    float4 a = *(const float4*)xp;
    float4 b = *(const float4*)(xp + 4);
    float s = a.x + a.y + a.z + a.w + b.x + b.y + b.z + b.w;
#pragma unroll
    for (int o = 16; o > 0; o >>= 1) s += __shfl_xor_sync(0xffffffffu, s, o);
    float mean = s * 0.00390625f;
    float q = 0.f;
    q += (a.x - mean) * (a.x - mean); q += (a.y - mean) * (a.y - mean);
    q += (a.z - mean) * (a.z - mean); q += (a.w - mean) * (a.w - mean);
    q += (b.x - mean) * (b.x - mean); q += (b.y - mean) * (b.y - mean);
    q += (b.z - mean) * (b.z - mean); q += (b.w - mean) * (b.w - mean);
#pragma unroll
    for (int o = 16; o > 0; o >>= 1) q += __shfl_xor_sync(0xffffffffu, q, o);
    float rstd = rsqrtf(q * 0.00390625f + 1e-5f);
    int c = lane * 8;
    float4 g0 = *(const float4*)(gw + c), g1 = *(const float4*)(gw + c + 4);
    float4 b0 = *(const float4*)(bw + c), b1 = *(const float4*)(bw + c + 4);
    float4 o0, o1;
    o0.x = (a.x - mean) * rstd * g0.x + b0.x;
    o0.y = (a.y - mean) * rstd * g0.y + b0.y;
    o0.z = (a.z - mean) * rstd * g0.z + b0.z;
    o0.w = (a.w - mean) * rstd * g0.w + b0.w;
    o1.x = (b.x - mean) * rstd * g1.x + b1.x;
    o1.y = (b.y - mean) * rstd * g1.y + b1.y;
    o1.z = (b.z - mean) * rstd * g1.z + b1.z;
    o1.w = (b.w - mean) * rstd * g1.w + b1.w;
    *(float4*)(Y + row * 256 + c)     = o0;
    *(float4*)(Y + row * 256 + c + 4) = o1;
}

// ---------------- cross-attention + fc + LN + output MLP, one CTA per batch ----------------
__global__ __launch_bounds__(256) void ca_kernel(
    const float* __restrict__ QH, const float* __restrict__ KH, const float* __restrict__ VH,
    const unsigned char* __restrict__ mask,
    const float* __restrict__ fcw, const float* __restrict__ fcb,
    const float* __restrict__ lng, const float* __restrict__ lnb,
    const float* __restrict__ src, const float* __restrict__ srct,
    const float* __restrict__ w1, const float* __restrict__ b1,
    const float* __restrict__ w2, const float* __restrict__ b2,
    float* __restrict__ out_vec, float* __restrict__ out_attn)
{
    const int b = blockIdx.x;
    const int tid = threadIdx.x;
    __shared__ float s_q[256], s_p[256], s_o[256], s_y[256], s_h[128], s_red[16];

    s_q[tid] = QH[(long)b * 256 + tid];
    __syncthreads();

    const int h = tid >> 7, k = tid & 127;
    const int lane = tid & 31, warp = tid >> 5;

    // scores
    const float* krow = KH + ((long)b * 128 + k) * 256 + h * 128;
    float s = 0.f;
#pragma unroll 8
    for (int d = 0; d < 128; d += 4) {
        float4 kv = *(const float4*)(krow + d);
        s += s_q[h * 128 + d + 0] * kv.x + s_q[h * 128 + d + 1] * kv.y
           + s_q[h * 128 + d + 2] * kv.z + s_q[h * 128 + d + 3] * kv.w;
    }
    s *= 0.0883883476483184f;
    if (mask[(long)b * 128 + k]) s = -1e10f;

    // softmax across each 128-thread head group (4 warps)
    float mx = s;
#pragma unroll
    for (int o = 16; o > 0; o >>= 1) mx = fmaxf(mx, __shfl_xor_sync(0xffffffffu, mx, o));
    if (lane == 0) s_red[warp] = mx;
    __syncthreads();
    mx = fmaxf(fmaxf(s_red[h * 4 + 0], s_red[h * 4 + 1]),
               fmaxf(s_red[h * 4 + 2], s_red[h * 4 + 3]));
    float e = expf(s - mx);
    float sum = e;
#pragma unroll
    for (int o = 16; o > 0; o >>= 1) sum += __shfl_xor_sync(0xffffffffu, sum, o);
    if (lane == 0) s_red[8 + warp] = sum;
    __syncthreads();
    sum = s_red[8 + h * 4 + 0] + s_red[8 + h * 4 + 1] + s_red[8 + h * 4 + 2] + s_red[8 + h * 4 + 3];
    float p = e / sum;
    s_p[tid] = p;
    out_attn[((long)h * BATCH + b) * 128 + k] = p;
    __syncthreads();

    // o = attn @ V   (thread = (h, d))
    const int d = tid & 127;
    float o = 0.f;
#pragma unroll 8
    for (int kk = 0; kk < 128; kk++)
        o += s_p[h * 128 + kk] * VH[((long)b * 128 + kk) * 256 + h * 128 + d];
    s_o[tid] = o;
    __syncthreads();

    // fc + bias + residual(q = concat(src, src_t))
    float y = fcb[tid];
    for (int i = 0; i < 256; i++) y += s_o[i] * fcw[i * 256 + tid];
    y += (tid < 128) ? src[(long)b * 128 + tid] : srct[(long)b * 128 + tid - 128];

    // LayerNorm over 256 (block reduce)
    float t = y;
#pragma unroll
    for (int ofs = 16; ofs > 0; ofs >>= 1) t += __shfl_xor_sync(0xffffffffu, t, ofs);
    if (lane == 0) s_red[warp] = t;
    __syncthreads();
    float mean = (s_red[0] + s_red[1] + s_red[2] + s_red[3] +
                  s_red[4] + s_red[5] + s_red[6] + s_red[7]) * 0.00390625f;
    float dv = y - mean;
    t = dv * dv;
#pragma unroll
    for (int ofs = 16; ofs > 0; ofs >>= 1) t += __shfl_xor_sync(0xffffffffu, t, ofs);
    if (lane == 0) s_red[8 + warp] = t;
    __syncthreads();
    float var = (s_red[8] + s_red[9] + s_red[10] + s_red[11] +
                 s_red[12] + s_red[13] + s_red[14] + s_red[15]) * 0.00390625f;
    float rstd = rsqrtf(var + 1e-5f);
    s_y[tid] = dv * rstd * lng[tid] + lnb[tid];
    __syncthreads();

    // output MLP: relu(concat(ca_out, src) @ w1 + b1) @ w2 + b2
    if (tid < 128) {
        float hh = b1[tid];
        for (int i = 0; i < 256; i++) hh += s_y[i] * w1[i * 128 + tid];
        for (int i = 0; i < 128; i++) hh += src[(long)b * 128 + i] * w1[(256 + i) * 128 + tid];
        s_h[tid] = fmaxf(hh, 0.f);
    }
    __syncthreads();
    if (tid < 128) {
        float oo = b2[tid];
        for (int i = 0; i < 128; i++) oo += s_h[i] * w2[i * 128 + tid];
        out_vec[(long)b * 128 + tid] = oo;
    }
}

// ---------------- host ----------------
static float* sym_addr(const void* s) {
    void* p = nullptr;
    cudaGetSymbolAddress(&p, s);
    return (float*)p;
}

extern "C" void kernel_launch(void* const* d_in, const int* in_sizes, int n_in,
                              void* d_out, int out_size)
{
    // Inputs 0-4 are the same in both candidate orderings.
    const float* src   = (const float*)d_in[0];
    const float* srct  = (const float*)d_in[1];
    const float* seq   = (const float*)d_in[2];
    const float* seqt  = (const float*)d_in[3];
    const void*  maskraw = d_in[4];

    const float *sa_wq, *sa_wk, *sa_wv, *sa_fcw, *sa_fcb, *sa_lng, *sa_lnb;
    const float *ms_w1, *ms_b1, *ms_w2, *ms_b2;
    const float *ca_wq, *ca_wk, *ca_wv, *ca_fcw, *ca_fcb, *ca_lng, *ca_lnb;
    const float *mg_w1, *mg_b1, *mg_w2, *mg_b2;

    // setup_inputs() dict order appends the 4 LN params LAST; the reference()
    // signature interleaves them. Disambiguate by element counts:
    // dict order:  in_sizes[10] = ms_w1 = 384*256 = 98304
    // sig  order:  in_sizes[10] = sa_lng = 256
    bool dict_order = (in_sizes[10] == 98304);
    if (dict_order) {
        sa_wq  = (const float*)d_in[5];
        sa_wk  = (const float*)d_in[6];
        sa_wv  = (const float*)d_in[7];
        sa_fcw = (const float*)d_in[8];
        sa_fcb = (const float*)d_in[9];
        ms_w1  = (const float*)d_in[10];
        ms_b1  = (const float*)d_in[11];
        ms_w2  = (const float*)d_in[12];
        ms_b2  = (const float*)d_in[13];
        ca_wq  = (const float*)d_in[14];
        ca_wk  = (const float*)d_in[15];
        ca_wv  = (const float*)d_in[16];
        ca_fcw = (const float*)d_in[17];
        ca_fcb = (const float*)d_in[18];
        mg_w1  = (const float*)d_in[19];
        mg_b1  = (const float*)d_in[20];
        mg_w2  = (const float*)d_in[21];
        mg_b2  = (const float*)d_in[22];
        sa_lng = (const float*)d_in[23];
        sa_lnb = (const float*)d_in[24];
        ca_lng = (const float*)d_in[25];
        ca_lnb = (const float*)d_in[26];
    } else {
        sa_wq  = (const float*)d_in[5];
        sa_wk  = (const float*)d_in[6];
        sa_wv  = (const float*)d_in[7];
        sa_fcw = (const float*)d_in[8];
        sa_fcb = (const float*)d_in[9];
        sa_lng = (const float*)d_in[10];
        sa_lnb = (const float*)d_in[11];
        ms_w1  = (const float*)d_in[12];
        ms_b1  = (const float*)d_in[13];
        ms_w2  = (const float*)d_in[14];
        ms_b2  = (const float*)d_in[15];
        ca_wq  = (const float*)d_in[16];
        ca_wk  = (const float*)d_in[17];
        ca_wv  = (const float*)d_in[18];
        ca_fcw = (const float*)d_in[19];
        ca_fcb = (const float*)d_in[20];
        ca_lng = (const float*)d_in[21];
        ca_lnb = (const float*)d_in[22];
        mg_w1  = (const float*)d_in[23];
        mg_b1  = (const float*)d_in[24];
        mg_w2  = (const float*)d_in[25];
        mg_b2  = (const float*)d_in[26];
    }
    float* out = (float*)d_out;

    float* KV = sym_addr(g_KV);
    float* Qb = sym_addr(g_Q);
    float* Kb = sym_addr(g_K);
    float* Vb = sym_addr(g_V);
    float* AO = sym_addr(g_AO);
    float* FC = sym_addr(g_FC);
    float* SA = sym_addr(g_SA);
    float* H1 = sym_addr(g_H1);
    float* KC = sym_addr(g_KC);
    float* KH = sym_addr(g_KH);
    float* VH = sym_addr(g_VH);
    float* QH = sym_addr(g_QH);
    unsigned char* MK = (unsigned char*)sym_addr(g_mask8);

    const int SMEM_ATTN = 3 * 128 * SST * 4;   // 202752 bytes
    cudaFuncSetAttribute(sa_attn_kernel, cudaFuncAttributeMaxDynamicSharedMemorySize, SMEM_ATTN);

    detect_mask_kernel<<<1, 32>>>(maskraw);
    norm_mask_kernel<<<NROWS / 256, 256>>>(maskraw);

    concat_kv_kernel<<<ELEMS / 4 / 256, 256>>>(seq, seqt);

    dim3 g2(2, NROWS / 128);   // (N tiles, M tiles)
    gemm_kernel<<<g2, 256>>>(KV, 256, 256, nullptr, 0, sa_wq, 256, 256, nullptr, nullptr, 0, Qb);
    gemm_kernel<<<g2, 256>>>(KV, 256, 256, nullptr, 0, sa_wk, 256, 256, nullptr, nullptr, 0, Kb);
    gemm_kernel<<<g2, 256>>>(KV, 256, 256, nullptr, 0, sa_wv, 256, 256, nullptr, nullptr, 0, Vb);

    dim3 ga(2, BATCH);         // (head, batch)
    sa_attn_kernel<<<ga, 256, SMEM_ATTN>>>(Qb, Kb, Vb, MK, AO);

    gemm_kernel<<<g2, 256>>>(AO, 256, 256, nullptr, 0, sa_fcw, 256, 256, sa_fcb, KV, 0, FC);
    ln_kernel<<<NROWS / 8, 256>>>(FC, sa_lng, sa_lnb, SA);

    gemm_kernel<<<g2, 256>>>(SA, 256, 256, seq, 128, ms_w1, 384, 256, ms_b1, nullptr, 1, H1);
    gemm_kernel<<<g2, 256>>>(H1, 256, 256, nullptr, 0, ms_w2, 256, 256, ms_b2, nullptr, 0, KC);

    gemm_kernel<<<g2, 256>>>(KC, 256, 256, nullptr, 0, ca_wk, 256, 256, nullptr, nullptr, 0, KH);
    gemm_kernel<<<g2, 256>>>(KC, 256, 256, nullptr, 0, ca_wv, 256, 256, nullptr, nullptr, 0, VH);

    dim3 gq(2, BATCH / 128);   // M=1024
    gemm_kernel<<<gq, 256>>>(src, 128, 128, srct, 128, ca_wq, 256, 256, nullptr, nullptr, 0, QH);

    ca_kernel<<<BATCH, 256>>>(QH, KH, VH, MK,
                              ca_fcw, ca_fcb, ca_lng, ca_lnb,
                              src, srct, mg_w1, mg_b1, mg_w2, mg_b2,
                              out, out + (long)BATCH * 128);
}

// round 4
// speedup vs baseline: 1.3802x; 1.3802x over previous
#include <cuda_runtime.h>
#include <math.h>

#define BATCH  1024
#define SEQN   128
#define DMODEL 256
#define NROWS  (BATCH*SEQN)            // 131072
#define ELEMS  (BATCH*SEQN*DMODEL)     // 33554432
#define SST    132                     // padded smem row stride (floats)

// GEMM tensor-core tile config
#define ASTR 36     // A smem row stride (u32)
#define BSTR 136    // B smem row stride (u32)
// smem u32 layout: Ah[128*36] Al[128*36] Bh[32*136] Bl[32*136]
#define SM_AH 0
#define SM_AL (128*ASTR)
#define SM_BH (2*128*ASTR)
#define SM_BL (2*128*ASTR + 32*BSTR)
#define SM_TOT_U32 (2*128*ASTR + 2*32*BSTR)   // 17920 u32 = 71680 B

// ---------------- scratch (static device allocations; allowed) ----------------
__device__ float g_KV[ELEMS];
__device__ float g_Q [ELEMS];
__device__ float g_K [ELEMS];
__device__ float g_V [ELEMS];
__device__ float g_AO[ELEMS];
__device__ float g_FC[ELEMS];
__device__ float g_SA[ELEMS];
__device__ float g_H1[ELEMS];
__device__ float g_KC[ELEMS];
__device__ float g_KH[ELEMS];
__device__ float g_VH[ELEMS];
__device__ float g_QH[BATCH*DMODEL];
__device__ unsigned char g_mask8[NROWS];
__device__ int g_mask_mode;

// ---------------- mask dtype detection + normalization ----------------
__global__ void detect_mask_kernel(const void* mask) {
    if (threadIdx.x == 0 && blockIdx.x == 0) {
        const unsigned* p = (const unsigned*)mask;
        int mode = 1;  // default int32
        for (int i = 0; i < 1024; i++) {
            unsigned v = p[i];
            if (v == 0x3F800000u) { mode = 2; break; }  // float32 1.0f
            if (v > 1u) { mode = 0; break; }            // packed uint8 bools
        }
        g_mask_mode = mode;
    }
}

__global__ __launch_bounds__(256) void norm_mask_kernel(const void* mask) {
    int i = blockIdx.x * 256 + threadIdx.x;
    if (i >= NROWS) return;
    int mode = g_mask_mode;
    unsigned char m;
    if (mode == 0)      m = (((const unsigned char*)mask)[i] != 0);
    else if (mode == 1) m = (((const int*)mask)[i] != 0);
    else                m = (((const float*)mask)[i] != 0.f);
    g_mask8[i] = m;
}

// ---------------- concat([seq, seq_t], -1) -> KV ----------------
__global__ __launch_bounds__(256) void concat_kv_kernel(
    const float* __restrict__ seq, const float* __restrict__ seqt)
{
    long i4 = (long)blockIdx.x * 256 + threadIdx.x;   // float4 index
    if (i4 >= (long)ELEMS / 4) return;
    long row = i4 >> 6;            // 64 float4 per 256-float row
    int  c4  = (int)(i4 & 63);
    float4 v;
    if (c4 < 32) v = ((const float4*)(seq  + row * 128))[c4];
    else         v = ((const float4*)(seqt + row * 128))[c4 - 32];
    ((float4*)(g_KV + row * 256))[c4] = v;
}

// ---------------- tf32 helpers ----------------
__device__ __forceinline__ unsigned cvt_tf32(float x) {
    unsigned u;
    asm("cvt.rna.tf32.f32 %0, %1;" : "=r"(u) : "f"(x));
    return u;
}
__device__ __forceinline__ void split_tf32(float x, unsigned& hi, unsigned& lo) {
    hi = cvt_tf32(x);
    lo = cvt_tf32(x - __uint_as_float(hi));
}
__device__ __forceinline__ void mma_tf32(float* d, const unsigned* a, const unsigned* b) {
    asm volatile(
        "mma.sync.aligned.m16n8k8.row.col.f32.tf32.tf32.f32 "
        "{%0,%1,%2,%3}, {%4,%5,%6,%7}, {%8,%9}, {%0,%1,%2,%3};\n"
        : "+f"(d[0]), "+f"(d[1]), "+f"(d[2]), "+f"(d[3])
        : "r"(a[0]), "r"(a[1]), "r"(a[2]), "r"(a[3]),
          "r"(b[0]), "r"(b[1]));
}

// ---------------- 3xTF32 tensor-core GEMM ----------------
// C[M,N] = concat(A1[:,0:K1], A2)[M,Ktot] @ W[Ktot,N]  (+bias)(+res)(relu)
// BM=128, BN=128, BK=32, 256 threads, warps 4(m) x 2(n), warp tile 32x64.
__global__ __launch_bounds__(256) void gemm_tc_kernel(
    const float* __restrict__ A1, int K1, int lda1,
    const float* __restrict__ A2, int lda2,
    const float* __restrict__ W, int Ktot, int Ncols,
    const float* __restrict__ bias,
    const float* __restrict__ res,
    int relu,
    float* __restrict__ C)
{
    extern __shared__ unsigned sm_u[];
    unsigned* sAh = sm_u + SM_AH;
    unsigned* sAl = sm_u + SM_AL;
    unsigned* sBh = sm_u + SM_BH;
    unsigned* sBl = sm_u + SM_BL;

    const int tid  = threadIdx.x;
    const int warp = tid >> 5, lane = tid & 31;
    const int wm = warp & 3, wn = warp >> 2;        // 4 x 2 warp grid
    const int group = lane >> 2, tig = lane & 3;
    const long m0 = (long)blockIdx.y * 128;
    const int  n0 = blockIdx.x * 128;
    const int wmb = wm * 32;
    const int wnb = wn * 64;

    float acc[2][8][4];
#pragma unroll
    for (int mi = 0; mi < 2; mi++)
#pragma unroll
        for (int ni = 0; ni < 8; ni++)
#pragma unroll
            for (int q = 0; q < 4; q++) acc[mi][ni][q] = 0.f;

    const int nk = Ktot / 32;
    float4 ra[4], rb[4];

    // prefetch chunk 0
    {
        const int k0 = 0;
#pragma unroll
        for (int i = 0; i < 4; i++) {
            int f4 = tid + i * 256;
            int row = f4 >> 3, c = (f4 & 7) * 4;
            const float* ap = (k0 < K1) ? (A1 + (m0 + row) * (long)lda1 + k0 + c)
                                        : (A2 + (m0 + row) * (long)lda2 + (k0 - K1) + c);
            ra[i] = *(const float4*)ap;
        }
#pragma unroll
        for (int i = 0; i < 4; i++) {
            int f4 = tid + i * 256;
            int row = f4 >> 5, c = (f4 & 31) * 4;
            rb[i] = *(const float4*)(W + (long)(k0 + row) * Ncols + n0 + c);
        }
    }

    for (int ck = 0; ck < nk; ck++) {
        __syncthreads();   // consumers of previous chunk done
        // split + store to smem
#pragma unroll
        for (int i = 0; i < 4; i++) {
            int f4 = tid + i * 256;
            int row = f4 >> 3, c = (f4 & 7) * 4;
            uint4 h, l;
            split_tf32(ra[i].x, h.x, l.x);
            split_tf32(ra[i].y, h.y, l.y);
            split_tf32(ra[i].z, h.z, l.z);
            split_tf32(ra[i].w, h.w, l.w);
            *(uint4*)&sAh[row * ASTR + c] = h;
            *(uint4*)&sAl[row * ASTR + c] = l;
        }
#pragma unroll
        for (int i = 0; i < 4; i++) {
            int f4 = tid + i * 256;
            int row = f4 >> 5, c = (f4 & 31) * 4;
            uint4 h, l;
            split_tf32(rb[i].x, h.x, l.x);
            split_tf32(rb[i].y, h.y, l.y);
            split_tf32(rb[i].z, h.z, l.z);
            split_tf32(rb[i].w, h.w, l.w);
            *(uint4*)&sBh[row * BSTR + c] = h;
            *(uint4*)&sBl[row * BSTR + c] = l;
        }
        __syncthreads();   // smem ready

        // prefetch next chunk (overlaps with MMA phase)
        if (ck + 1 < nk) {
            const int k0 = (ck + 1) * 32;
#pragma unroll
            for (int i = 0; i < 4; i++) {
                int f4 = tid + i * 256;
                int row = f4 >> 3, c = (f4 & 7) * 4;
                const float* ap = (k0 < K1) ? (A1 + (m0 + row) * (long)lda1 + k0 + c)
                                            : (A2 + (m0 + row) * (long)lda2 + (k0 - K1) + c);
                ra[i] = *(const float4*)ap;
            }
#pragma unroll
            for (int i = 0; i < 4; i++) {
                int f4 = tid + i * 256;
                int row = f4 >> 5, c = (f4 & 31) * 4;
                rb[i] = *(const float4*)(W + (long)(k0 + row) * Ncols + n0 + c);
            }
        }

        // compute 4 k-steps of 8
#pragma unroll
        for (int ks = 0; ks < 4; ks++) {
            const int kb = ks * 8;
            unsigned af[2][4], alf[2][4];
#pragma unroll
            for (int mi = 0; mi < 2; mi++) {
                int r = wmb + mi * 16 + group;
                af[mi][0]  = sAh[r * ASTR + kb + tig];
                af[mi][1]  = sAh[(r + 8) * ASTR + kb + tig];
                af[mi][2]  = sAh[r * ASTR + kb + tig + 4];
                af[mi][3]  = sAh[(r + 8) * ASTR + kb + tig + 4];
                alf[mi][0] = sAl[r * ASTR + kb + tig];
                alf[mi][1] = sAl[(r + 8) * ASTR + kb + tig];
                alf[mi][2] = sAl[r * ASTR + kb + tig + 4];
                alf[mi][3] = sAl[(r + 8) * ASTR + kb + tig + 4];
            }
#pragma unroll
            for (int half = 0; half < 2; half++) {
                unsigned bf[4][2], blf[4][2];
#pragma unroll
                for (int j = 0; j < 4; j++) {
                    int col = wnb + (half * 4 + j) * 8 + group;
                    bf[j][0]  = sBh[(kb + tig) * BSTR + col];
                    bf[j][1]  = sBh[(kb + tig + 4) * BSTR + col];
                    blf[j][0] = sBl[(kb + tig) * BSTR + col];
                    blf[j][1] = sBl[(kb + tig + 4) * BSTR + col];
                }
#pragma unroll
                for (int mi = 0; mi < 2; mi++)
#pragma unroll
                    for (int j = 0; j < 4; j++) {
                        int ni = half * 4 + j;
                        mma_tf32(acc[mi][ni], af[mi],  bf[j]);
                        mma_tf32(acc[mi][ni], alf[mi], bf[j]);
                        mma_tf32(acc[mi][ni], af[mi],  blf[j]);
                    }
            }
        }
    }

    // epilogue
#pragma unroll
    for (int mi = 0; mi < 2; mi++) {
        long gm = m0 + wmb + mi * 16 + group;
#pragma unroll
        for (int ni = 0; ni < 8; ni++) {
            int gc = n0 + wnb + ni * 8 + 2 * tig;
            float v0 = acc[mi][ni][0], v1 = acc[mi][ni][1];
            float v2 = acc[mi][ni][2], v3 = acc[mi][ni][3];
            if (bias) {
                float b0 = bias[gc], b1 = bias[gc + 1];
                v0 += b0; v1 += b1; v2 += b0; v3 += b1;
            }
            if (res) {
                float2 r0 = *(const float2*)(res + gm * Ncols + gc);
                float2 r1 = *(const float2*)(res + (gm + 8) * Ncols + gc);
                v0 += r0.x; v1 += r0.y; v2 += r1.x; v3 += r1.y;
            }
            if (relu) {
                v0 = fmaxf(v0, 0.f); v1 = fmaxf(v1, 0.f);
                v2 = fmaxf(v2, 0.f); v3 = fmaxf(v3, 0.f);
            }
            *(float2*)(C + gm * Ncols + gc)       = make_float2(v0, v1);
            *(float2*)(C + (gm + 8) * Ncols + gc) = make_float2(v2, v3);
        }
    }
}

// ---------------- self-attention: one CTA per (head, batch) ----------------
__global__ __launch_bounds__(256) void sa_attn_kernel(
    const float* __restrict__ Q, const float* __restrict__ K, const float* __restrict__ V,
    const unsigned char* __restrict__ mask, float* __restrict__ O)
{
    extern __shared__ float sm[];
    float* Qt = sm;                  // [128][SST]
    float* Kt = sm + 128 * SST;      // [128][SST]
    float* Pt = sm + 2 * 128 * SST;  // [128][SST]  scores stored [k][q]
    __shared__ unsigned char smask[128];

    const int h = blockIdx.x, b = blockIdx.y;
    const int tid = threadIdx.x;
    const float* Qp = Q + ((long)b * SEQN) * DMODEL + h * 128;
    const float* Kp = K + ((long)b * SEQN) * DMODEL + h * 128;
    const float* Vp = V + ((long)b * SEQN) * DMODEL + h * 128;

    if (tid < 128) smask[tid] = mask[(long)b * SEQN + tid];
    for (int idx = tid; idx < 128 * 32; idx += 256) {
        int r = idx >> 5;
        int c = (idx & 31) << 2;
        float4 qv = *(const float4*)(Qp + (long)r * DMODEL + c);
        Qt[(c + 0) * SST + r] = qv.x; Qt[(c + 1) * SST + r] = qv.y;
        Qt[(c + 2) * SST + r] = qv.z; Qt[(c + 3) * SST + r] = qv.w;
        float4 kv = *(const float4*)(Kp + (long)r * DMODEL + c);
        Kt[(c + 0) * SST + r] = kv.x; Kt[(c + 1) * SST + r] = kv.y;
        Kt[(c + 2) * SST + r] = kv.z; Kt[(c + 3) * SST + r] = kv.w;
    }
    __syncthreads();

    const int tx = tid & 15, ty = tid >> 4;
    float acc[8][8];
#pragma unroll
    for (int i = 0; i < 8; i++)
#pragma unroll
        for (int j = 0; j < 8; j++) acc[i][j] = 0.f;
    for (int k = 0; k < 128; k++) {
        float a[8], bb[8];
#pragma unroll
        for (int i = 0; i < 8; i++) a[i]  = Qt[k * SST + ty * 8 + i];
#pragma unroll
        for (int j = 0; j < 8; j++) bb[j] = Kt[k * SST + tx * 8 + j];
#pragma unroll
        for (int i = 0; i < 8; i++)
#pragma unroll
            for (int j = 0; j < 8; j++)
                acc[i][j] = fmaf(a[i], bb[j], acc[i][j]);
    }
    // store transposed: Pt[key][query]
#pragma unroll
    for (int i = 0; i < 8; i++)
#pragma unroll
        for (int j = 0; j < 8; j++)
            Pt[(tx * 8 + j) * SST + ty * 8 + i] = acc[i][j];
    __syncthreads();

    // overlap: load V into Qt while doing softmax on Pt
    for (int idx = tid; idx < 128 * 32; idx += 256) {
        int r = idx >> 5;
        int c = (idx & 31) << 2;
        *(float4*)&Qt[r * SST + c] = *(const float4*)(Vp + (long)r * DMODEL + c);
    }
    const float invs = 0.0883883476483184f;  // 1/sqrt(128)
    const int warp = tid >> 5, lane = tid & 31;
    for (int r = warp; r < 128; r += 8) {     // r = query row
        float vv[4];
        float mx = -1e30f;
#pragma unroll
        for (int q = 0; q < 4; q++) {
            int c = lane + q * 32;            // key index
            float s = Pt[c * SST + r] * invs;
            if (smask[c]) s = -1e10f;
            vv[q] = s; mx = fmaxf(mx, s);
        }
#pragma unroll
        for (int o = 16; o > 0; o >>= 1) mx = fmaxf(mx, __shfl_xor_sync(0xffffffffu, mx, o));
        float sum = 0.f;
#pragma unroll
        for (int q = 0; q < 4; q++) { vv[q] = expf(vv[q] - mx); sum += vv[q]; }
#pragma unroll
        for (int o = 16; o > 0; o >>= 1) sum += __shfl_xor_sync(0xffffffffu, sum, o);
        float rs = 1.f / sum;
#pragma unroll
        for (int q = 0; q < 4; q++) Pt[(lane + q * 32) * SST + r] = vv[q] * rs;
    }
    __syncthreads();

    // O = P @ V
    float oc[8][8];
#pragma unroll
    for (int i = 0; i < 8; i++)
#pragma unroll
        for (int j = 0; j < 8; j++) oc[i][j] = 0.f;
    for (int k = 0; k < 128; k++) {
        float a[8], bb[8];
#pragma unroll
        for (int i = 0; i < 8; i++) a[i]  = Pt[k * SST + ty * 8 + i];
#pragma unroll
        for (int j = 0; j < 8; j++) bb[j] = Qt[k * SST + tx * 8 + j];
#pragma unroll
        for (int i = 0; i < 8; i++)
#pragma unroll
            for (int j = 0; j < 8; j++)
                oc[i][j] = fmaf(a[i], bb[j], oc[i][j]);
    }
    float* Op = O + ((long)b * SEQN) * DMODEL + h * 128;
#pragma unroll
    for (int i = 0; i < 8; i++) {
        *(float4*)(Op + (long)(ty * 8 + i) * DMODEL + tx * 8)     = make_float4(oc[i][0], oc[i][1], oc[i][2], oc[i][3]);
        *(float4*)(Op + (long)(ty * 8 + i) * DMODEL + tx * 8 + 4) = make_float4(oc[i][4], oc[i][5], oc[i][6], oc[i][7]);
    }
}

// ---------------- LayerNorm over 256, warp per row ----------------
__global__ __launch_bounds__(256) void ln_kernel(
    const float* __restrict__ X, const float* __restrict__ gw,
    const float* __restrict__ bw, float* __restrict__ Y)
{
    long row = (long)blockIdx.x * 8 + (threadIdx.x >> 5);
    int lane = threadIdx.x & 31;
    const float* xp = X + row * 256 + lane * 8;
    float4 a = *(const float4*)xp;
    float4 b = *(const float4*)(xp + 4);
    float s = a.x + a.y + a.z + a.w + b.x + b.y + b.z + b.w;
#pragma unroll
    for (int o = 16; o > 0; o >>= 1) s += __shfl_xor_sync(0xffffffffu, s, o);
    float mean = s * 0.00390625f;
    float q = 0.f;
    q += (a.x - mean) * (a.x - mean); q += (a.y - mean) * (a.y - mean);
    q += (a.z - mean) * (a.z - mean); q += (a.w - mean) * (a.w - mean);
    q += (b.x - mean) * (b.x - mean); q += (b.y - mean) * (b.y - mean);
    q += (b.z - mean) * (b.z - mean); q += (b.w - mean) * (b.w - mean);
#pragma unroll
    for (int o = 16; o > 0; o >>= 1) q += __shfl_xor_sync(0xffffffffu, q, o);
    float rstd = rsqrtf(q * 0.00390625f + 1e-5f);
    int c = lane * 8;
    float4 g0 = *(const float4*)(gw + c), g1 = *(const float4*)(gw + c + 4);
    float4 b0 = *(const float4*)(bw + c), b1 = *(const float4*)(bw + c + 4);
    float4 o0, o1;
    o0.x = (a.x - mean) * rstd * g0.x + b0.x;
    o0.y = (a.y - mean) * rstd * g0.y + b0.y;
    o0.z = (a.z - mean) * rstd * g0.z + b0.z;
    o0.w = (a.w - mean) * rstd * g0.w + b0.w;
    o1.x = (b.x - mean) * rstd * g1.x + b1.x;
    o1.y = (b.y - mean) * rstd * g1.y + b1.y;
    o1.z = (b.z - mean) * rstd * g1.z + b1.z;
    o1.w = (b.w - mean) * rstd * g1.w + b1.w;
    *(float4*)(Y + row * 256 + c)     = o0;
    *(float4*)(Y + row * 256 + c + 4) = o1;
}

// ---------------- cross-attention + fc + LN + output MLP, one CTA per batch ----------------
__global__ __launch_bounds__(256) void ca_kernel(
    const float* __restrict__ QH, const float* __restrict__ KH, const float* __restrict__ VH,
    const unsigned char* __restrict__ mask,
    const float* __restrict__ fcw, const float* __restrict__ fcb,
    const float* __restrict__ lng, const float* __restrict__ lnb,
    const float* __restrict__ src, const float* __restrict__ srct,
    const float* __restrict__ w1, const float* __restrict__ b1,
    const float* __restrict__ w2, const float* __restrict__ b2,
    float* __restrict__ out_vec, float* __restrict__ out_attn)
{
    const int b = blockIdx.x;
    const int tid = threadIdx.x;
    __shared__ float s_q[256], s_p[256], s_o[256], s_y[256], s_h[128], s_red[16];

    s_q[tid] = QH[(long)b * 256 + tid];
    __syncthreads();

    const int h = tid >> 7, k = tid & 127;
    const int lane = tid & 31, warp = tid >> 5;

    // scores
    const float* krow = KH + ((long)b * 128 + k) * 256 + h * 128;
    float s = 0.f;
#pragma unroll 8
    for (int d = 0; d < 128; d += 4) {
        float4 kv = *(const float4*)(krow + d);
        s += s_q[h * 128 + d + 0] * kv.x + s_q[h * 128 + d + 1] * kv.y
           + s_q[h * 128 + d + 2] * kv.z + s_q[h * 128 + d + 3] * kv.w;
    }
    s *= 0.0883883476483184f;
    if (mask[(long)b * 128 + k]) s = -1e10f;

    // softmax across each 128-thread head group (4 warps)
    float mx = s;
#pragma unroll
    for (int o = 16; o > 0; o >>= 1) mx = fmaxf(mx, __shfl_xor_sync(0xffffffffu, mx, o));
    if (lane == 0) s_red[warp] = mx;
    __syncthreads();
    mx = fmaxf(fmaxf(s_red[h * 4 + 0], s_red[h * 4 + 1]),
               fmaxf(s_red[h * 4 + 2], s_red[h * 4 + 3]));
    float e = expf(s - mx);
    float sum = e;
#pragma unroll
    for (int o = 16; o > 0; o >>= 1) sum += __shfl_xor_sync(0xffffffffu, sum, o);
    if (lane == 0) s_red[8 + warp] = sum;
    __syncthreads();
    sum = s_red[8 + h * 4 + 0] + s_red[8 + h * 4 + 1] + s_red[8 + h * 4 + 2] + s_red[8 + h * 4 + 3];
    float p = e / sum;
    s_p[tid] = p;
    out_attn[((long)h * BATCH + b) * 128 + k] = p;
    __syncthreads();

    // o = attn @ V   (thread = (h, d))
    const int d = tid & 127;
    float o = 0.f;
#pragma unroll 8
    for (int kk = 0; kk < 128; kk++)
        o += s_p[h * 128 + kk] * VH[((long)b * 128 + kk) * 256 + h * 128 + d];
    s_o[tid] = o;
    __syncthreads();

    // fc + bias + residual(q = concat(src, src_t))
    float y = fcb[tid];
    for (int i = 0; i < 256; i++) y += s_o[i] * fcw[i * 256 + tid];
    y += (tid < 128) ? src[(long)b * 128 + tid] : srct[(long)b * 128 + tid - 128];

    // LayerNorm over 256 (block reduce)
    float t = y;
#pragma unroll
    for (int ofs = 16; ofs > 0; ofs >>= 1) t += __shfl_xor_sync(0xffffffffu, t, ofs);
    if (lane == 0) s_red[warp] = t;
    __syncthreads();
    float mean = (s_red[0] + s_red[1] + s_red[2] + s_red[3] +
                  s_red[4] + s_red[5] + s_red[6] + s_red[7]) * 0.00390625f;
    float dv = y - mean;
    t = dv * dv;
#pragma unroll
    for (int ofs = 16; ofs > 0; ofs >>= 1) t += __shfl_xor_sync(0xffffffffu, t, ofs);
    if (lane == 0) s_red[8 + warp] = t;
    __syncthreads();
    float var = (s_red[8] + s_red[9] + s_red[10] + s_red[11] +
                 s_red[12] + s_red[13] + s_red[14] + s_red[15]) * 0.00390625f;
    float rstd = rsqrtf(var + 1e-5f);
    s_y[tid] = dv * rstd * lng[tid] + lnb[tid];
    __syncthreads();

    // output MLP: relu(concat(ca_out, src) @ w1 + b1) @ w2 + b2
    if (tid < 128) {
        float hh = b1[tid];
        for (int i = 0; i < 256; i++) hh += s_y[i] * w1[i * 128 + tid];
        for (int i = 0; i < 128; i++) hh += src[(long)b * 128 + i] * w1[(256 + i) * 128 + tid];
        s_h[tid] = fmaxf(hh, 0.f);
    }
    __syncthreads();
    if (tid < 128) {
        float oo = b2[tid];
        for (int i = 0; i < 128; i++) oo += s_h[i] * w2[i * 128 + tid];
        out_vec[(long)b * 128 + tid] = oo;
    }
}

// ---------------- host ----------------
static float* sym_addr(const void* s) {
    void* p = nullptr;
    cudaGetSymbolAddress(&p, s);
    return (float*)p;
}

extern "C" void kernel_launch(void* const* d_in, const int* in_sizes, int n_in,
                              void* d_out, int out_size)
{
    // Inputs 0-4 are the same in both candidate orderings.
    const float* src   = (const float*)d_in[0];
    const float* srct  = (const float*)d_in[1];
    const float* seq   = (const float*)d_in[2];
    const float* seqt  = (const float*)d_in[3];
    const void*  maskraw = d_in[4];

    const float *sa_wq, *sa_wk, *sa_wv, *sa_fcw, *sa_fcb, *sa_lng, *sa_lnb;
    const float *ms_w1, *ms_b1, *ms_w2, *ms_b2;
    const float *ca_wq, *ca_wk, *ca_wv, *ca_fcw, *ca_fcb, *ca_lng, *ca_lnb;
    const float *mg_w1, *mg_b1, *mg_w2, *mg_b2;

    bool dict_order = (in_sizes[10] == 98304);
    if (dict_order) {
        sa_wq  = (const float*)d_in[5];
        sa_wk  = (const float*)d_in[6];
        sa_wv  = (const float*)d_in[7];
        sa_fcw = (const float*)d_in[8];
        sa_fcb = (const float*)d_in[9];
        ms_w1  = (const float*)d_in[10];
        ms_b1  = (const float*)d_in[11];
        ms_w2  = (const float*)d_in[12];
        ms_b2  = (const float*)d_in[13];
        ca_wq  = (const float*)d_in[14];
        ca_wk  = (const float*)d_in[15];
        ca_wv  = (const float*)d_in[16];
        ca_fcw = (const float*)d_in[17];
        ca_fcb = (const float*)d_in[18];
        mg_w1  = (const float*)d_in[19];
        mg_b1  = (const float*)d_in[20];
        mg_w2  = (const float*)d_in[21];
        mg_b2  = (const float*)d_in[22];
        sa_lng = (const float*)d_in[23];
        sa_lnb = (const float*)d_in[24];
        ca_lng = (const float*)d_in[25];
        ca_lnb = (const float*)d_in[26];
    } else {
        sa_wq  = (const float*)d_in[5];
        sa_wk  = (const float*)d_in[6];
        sa_wv  = (const float*)d_in[7];
        sa_fcw = (const float*)d_in[8];
        sa_fcb = (const float*)d_in[9];
        sa_lng = (const float*)d_in[10];
        sa_lnb = (const float*)d_in[11];
        ms_w1  = (const float*)d_in[12];
        ms_b1  = (const float*)d_in[13];
        ms_w2  = (const float*)d_in[14];
        ms_b2  = (const float*)d_in[15];
        ca_wq  = (const float*)d_in[16];
        ca_wk  = (const float*)d_in[17];
        ca_wv  = (const float*)d_in[18];
        ca_fcw = (const float*)d_in[19];
        ca_fcb = (const float*)d_in[20];
        ca_lng = (const float*)d_in[21];
        ca_lnb = (const float*)d_in[22];
        mg_w1  = (const float*)d_in[23];
        mg_b1  = (const float*)d_in[24];
        mg_w2  = (const float*)d_in[25];
        mg_b2  = (const float*)d_in[26];
    }
    float* out = (float*)d_out;

    float* KV = sym_addr(g_KV);
    float* Qb = sym_addr(g_Q);
    float* Kb = sym_addr(g_K);
    float* Vb = sym_addr(g_V);
    float* AO = sym_addr(g_AO);
    float* FC = sym_addr(g_FC);
    float* SA = sym_addr(g_SA);
    float* H1 = sym_addr(g_H1);
    float* KC = sym_addr(g_KC);
    float* KH = sym_addr(g_KH);
    float* VH = sym_addr(g_VH);
    float* QH = sym_addr(g_QH);
    unsigned char* MK = (unsigned char*)sym_addr(g_mask8);

    const int SMEM_ATTN = 3 * 128 * SST * 4;   // 202752 bytes
    cudaFuncSetAttribute(sa_attn_kernel, cudaFuncAttributeMaxDynamicSharedMemorySize, SMEM_ATTN);
    const int SMEM_GEMM = SM_TOT_U32 * 4;      // 71680 bytes
    cudaFuncSetAttribute(gemm_tc_kernel, cudaFuncAttributeMaxDynamicSharedMemorySize, SMEM_GEMM);

    detect_mask_kernel<<<1, 32>>>(maskraw);
    norm_mask_kernel<<<NROWS / 256, 256>>>(maskraw);

    concat_kv_kernel<<<ELEMS / 4 / 256, 256>>>(seq, seqt);

    dim3 g2(2, NROWS / 128);   // (N tiles, M tiles)
    gemm_tc_kernel<<<g2, 256, SMEM_GEMM>>>(KV, 256, 256, nullptr, 0, sa_wq, 256, 256, nullptr, nullptr, 0, Qb);
    gemm_tc_kernel<<<g2, 256, SMEM_GEMM>>>(KV, 256, 256, nullptr, 0, sa_wk, 256, 256, nullptr, nullptr, 0, Kb);
    gemm_tc_kernel<<<g2, 256, SMEM_GEMM>>>(KV, 256, 256, nullptr, 0, sa_wv, 256, 256, nullptr, nullptr, 0, Vb);

    dim3 ga(2, BATCH);         // (head, batch)
    sa_attn_kernel<<<ga, 256, SMEM_ATTN>>>(Qb, Kb, Vb, MK, AO);

    gemm_tc_kernel<<<g2, 256, SMEM_GEMM>>>(AO, 256, 256, nullptr, 0, sa_fcw, 256, 256, sa_fcb, KV, 0, FC);
    ln_kernel<<<NROWS / 8, 256>>>(FC, sa_lng, sa_lnb, SA);

    gemm_tc_kernel<<<g2, 256, SMEM_GEMM>>>(SA, 256, 256, seq, 128, ms_w1, 384, 256, ms_b1, nullptr, 1, H1);
    gemm_tc_kernel<<<g2, 256, SMEM_GEMM>>>(H1, 256, 256, nullptr, 0, ms_w2, 256, 256, ms_b2, nullptr, 0, KC);

    gemm_tc_kernel<<<g2, 256, SMEM_GEMM>>>(KC, 256, 256, nullptr, 0, ca_wk, 256, 256, nullptr, nullptr, 0, KH);
    gemm_tc_kernel<<<g2, 256, SMEM_GEMM>>>(KC, 256, 256, nullptr, 0, ca_wv, 256, 256, nullptr, nullptr, 0, VH);

    dim3 gq(2, BATCH / 128);   // M=1024
    gemm_tc_kernel<<<gq, 256, SMEM_GEMM>>>(src, 128, 128, srct, 128, ca_wq, 256, 256, nullptr, nullptr, 0, QH);

    ca_kernel<<<BATCH, 256>>>(QH, KH, VH, MK,
                              ca_fcw, ca_fcb, ca_lng, ca_lnb,
                              src, srct, mg_w1, mg_b1, mg_w2, mg_b2,
                              out, out + (long)BATCH * 128);
}

// round 5
// speedup vs baseline: 1.3874x; 1.0052x over previous
#include <cuda_runtime.h>
#include <math.h>

#define BATCH  1024
#define SEQN   128
#define DMODEL 256
#define NROWS  (BATCH*SEQN)            // 131072
#define ELEMS  (BATCH*SEQN*DMODEL)     // 33554432
#define SST    132                     // padded smem row stride (floats)

// GEMM tensor-core tile config (per stage)
#define ASTR 36     // A smem row stride (u32)
#define BSTR 136    // B smem row stride (u32)
#define SM_AH 0
#define SM_AL (128*ASTR)
#define SM_BH (2*128*ASTR)
#define SM_BL (2*128*ASTR + 32*BSTR)
#define SM_STAGE_U32 (2*128*ASTR + 2*32*BSTR)   // 17920 u32 = 71680 B per stage

// ---------------- scratch ----------------
__device__ float g_KV[ELEMS];
__device__ float g_Q [ELEMS];
__device__ float g_K [ELEMS];
__device__ float g_V [ELEMS];
__device__ float g_AO[ELEMS];
__device__ float g_FC[ELEMS];
__device__ float g_SA[ELEMS];
__device__ float g_H1[ELEMS];
__device__ float g_KC[ELEMS];
__device__ float g_KH[ELEMS];
__device__ float g_VH[ELEMS];
__device__ float g_QH[BATCH*DMODEL];
__device__ unsigned char g_mask8[NROWS];
__device__ int g_mask_mode;

// ---------------- mask dtype detection + normalization ----------------
__global__ void detect_mask_kernel(const void* mask) {
    if (threadIdx.x == 0 && blockIdx.x == 0) {
        const unsigned* p = (const unsigned*)mask;
        int mode = 1;
        for (int i = 0; i < 1024; i++) {
            unsigned v = p[i];
            if (v == 0x3F800000u) { mode = 2; break; }
            if (v > 1u) { mode = 0; break; }
        }
        g_mask_mode = mode;
    }
}

__global__ __launch_bounds__(256) void norm_mask_kernel(const void* mask) {
    int i = blockIdx.x * 256 + threadIdx.x;
    if (i >= NROWS) return;
    int mode = g_mask_mode;
    unsigned char m;
    if (mode == 0)      m = (((const unsigned char*)mask)[i] != 0);
    else if (mode == 1) m = (((const int*)mask)[i] != 0);
    else                m = (((const float*)mask)[i] != 0.f);
    g_mask8[i] = m;
}

// ---------------- concat([seq, seq_t], -1) -> KV ----------------
__global__ __launch_bounds__(256) void concat_kv_kernel(
    const float* __restrict__ seq, const float* __restrict__ seqt)
{
    long i4 = (long)blockIdx.x * 256 + threadIdx.x;
    if (i4 >= (long)ELEMS / 4) return;
    long row = i4 >> 6;
    int  c4  = (int)(i4 & 63);
    float4 v;
    if (c4 < 32) v = ((const float4*)(seq  + row * 128))[c4];
    else         v = ((const float4*)(seqt + row * 128))[c4 - 32];
    ((float4*)(g_KV + row * 256))[c4] = v;
}

// ---------------- tf32 helpers ----------------
__device__ __forceinline__ unsigned cvt_tf32(float x) {
    unsigned u;
    asm("cvt.rna.tf32.f32 %0, %1;" : "=r"(u) : "f"(x));
    return u;
}
__device__ __forceinline__ void split_tf32(float x, unsigned& hi, unsigned& lo) {
    hi = cvt_tf32(x);
    lo = cvt_tf32(x - __uint_as_float(hi));
}
__device__ __forceinline__ void mma_tf32(float* d, const unsigned* a, const unsigned* b) {
    asm volatile(
        "mma.sync.aligned.m16n8k8.row.col.f32.tf32.tf32.f32 "
        "{%0,%1,%2,%3}, {%4,%5,%6,%7}, {%8,%9}, {%0,%1,%2,%3};\n"
        : "+f"(d[0]), "+f"(d[1]), "+f"(d[2]), "+f"(d[3])
        : "r"(a[0]), "r"(a[1]), "r"(a[2]), "r"(a[3]),
          "r"(b[0]), "r"(b[1]));
}

// ---------------- 3xTF32 tensor-core GEMM, double-buffered smem ----------------
__device__ __forceinline__ void g_load(
    const float* __restrict__ A1, int K1, int lda1,
    const float* __restrict__ A2, int lda2,
    const float* __restrict__ W, int Ncols,
    long m0, int n0, int tid, int k0, float4* ra, float4* rb)
{
#pragma unroll
    for (int i = 0; i < 4; i++) {
        int f4 = tid + i * 256;
        int row = f4 >> 3, c = (f4 & 7) * 4;
        const float* ap = (k0 < K1) ? (A1 + (m0 + row) * (long)lda1 + k0 + c)
                                    : (A2 + (m0 + row) * (long)lda2 + (k0 - K1) + c);
        ra[i] = *(const float4*)ap;
    }
#pragma unroll
    for (int i = 0; i < 4; i++) {
        int f4 = tid + i * 256;
        int row = f4 >> 5, c = (f4 & 31) * 4;
        rb[i] = *(const float4*)(W + (long)(k0 + row) * Ncols + n0 + c);
    }
}

__device__ __forceinline__ void g_store(unsigned* st, int tid, const float4* ra, const float4* rb)
{
    unsigned* sAh = st + SM_AH;
    unsigned* sAl = st + SM_AL;
    unsigned* sBh = st + SM_BH;
    unsigned* sBl = st + SM_BL;
#pragma unroll
    for (int i = 0; i < 4; i++) {
        int f4 = tid + i * 256;
        int row = f4 >> 3, c = (f4 & 7) * 4;
        uint4 h, l;
        split_tf32(ra[i].x, h.x, l.x);
        split_tf32(ra[i].y, h.y, l.y);
        split_tf32(ra[i].z, h.z, l.z);
        split_tf32(ra[i].w, h.w, l.w);
        *(uint4*)&sAh[row * ASTR + c] = h;
        *(uint4*)&sAl[row * ASTR + c] = l;
    }
#pragma unroll
    for (int i = 0; i < 4; i++) {
        int f4 = tid + i * 256;
        int row = f4 >> 5, c = (f4 & 31) * 4;
        uint4 h, l;
        split_tf32(rb[i].x, h.x, l.x);
        split_tf32(rb[i].y, h.y, l.y);
        split_tf32(rb[i].z, h.z, l.z);
        split_tf32(rb[i].w, h.w, l.w);
        *(uint4*)&sBh[row * BSTR + c] = h;
        *(uint4*)&sBl[row * BSTR + c] = l;
    }
}

__global__ __launch_bounds__(256) void gemm_tc_kernel(
    const float* __restrict__ A1, int K1, int lda1,
    const float* __restrict__ A2, int lda2,
    const float* __restrict__ W, int Ktot, int Ncols,
    const float* __restrict__ bias,
    const float* __restrict__ res,
    int relu,
    float* __restrict__ C)
{
    extern __shared__ unsigned sm_u[];
    const int tid  = threadIdx.x;
    const int warp = tid >> 5, lane = tid & 31;
    const int wm = warp & 3, wn = warp >> 2;
    const int group = lane >> 2, tig = lane & 3;
    const long m0 = (long)blockIdx.y * 128;
    const int  n0 = blockIdx.x * 128;
    const int wmb = wm * 32;
    const int wnb = wn * 64;

    float acc[2][8][4];
#pragma unroll
    for (int mi = 0; mi < 2; mi++)
#pragma unroll
        for (int ni = 0; ni < 8; ni++)
#pragma unroll
            for (int q = 0; q < 4; q++) acc[mi][ni][q] = 0.f;

    const int nk = Ktot / 32;
    float4 ra[4], rb[4];

    // prologue: stage chunk 0
    g_load(A1, K1, lda1, A2, lda2, W, Ncols, m0, n0, tid, 0, ra, rb);
    g_store(sm_u, tid, ra, rb);
    __syncthreads();

    for (int ck = 0; ck < nk; ck++) {
        // kick global loads for next chunk (hidden behind MMA phase)
        if (ck + 1 < nk)
            g_load(A1, K1, lda1, A2, lda2, W, Ncols, m0, n0, tid, (ck + 1) * 32, ra, rb);

        unsigned* st = sm_u + (ck & 1) * SM_STAGE_U32;
        unsigned* sAh = st + SM_AH;
        unsigned* sAl = st + SM_AL;
        unsigned* sBh = st + SM_BH;
        unsigned* sBl = st + SM_BL;

#pragma unroll
        for (int ks = 0; ks < 4; ks++) {
            const int kb = ks * 8;
            unsigned af[2][4], alf[2][4];
#pragma unroll
            for (int mi = 0; mi < 2; mi++) {
                int r = wmb + mi * 16 + group;
                af[mi][0]  = sAh[r * ASTR + kb + tig];
                af[mi][1]  = sAh[(r + 8) * ASTR + kb + tig];
                af[mi][2]  = sAh[r * ASTR + kb + tig + 4];
                af[mi][3]  = sAh[(r + 8) * ASTR + kb + tig + 4];
                alf[mi][0] = sAl[r * ASTR + kb + tig];
                alf[mi][1] = sAl[(r + 8) * ASTR + kb + tig];
                alf[mi][2] = sAl[r * ASTR + kb + tig + 4];
                alf[mi][3] = sAl[(r + 8) * ASTR + kb + tig + 4];
            }
#pragma unroll
            for (int half = 0; half < 2; half++) {
                unsigned bf[4][2], blf[4][2];
#pragma unroll
                for (int j = 0; j < 4; j++) {
                    int col = wnb + (half * 4 + j) * 8 + group;
                    bf[j][0]  = sBh[(kb + tig) * BSTR + col];
                    bf[j][1]  = sBh[(kb + tig + 4) * BSTR + col];
                    blf[j][0] = sBl[(kb + tig) * BSTR + col];
                    blf[j][1] = sBl[(kb + tig + 4) * BSTR + col];
                }
#pragma unroll
                for (int mi = 0; mi < 2; mi++)
#pragma unroll
                    for (int j = 0; j < 4; j++) {
                        int ni = half * 4 + j;
                        mma_tf32(acc[mi][ni], af[mi],  bf[j]);
                        mma_tf32(acc[mi][ni], alf[mi], bf[j]);
                        mma_tf32(acc[mi][ni], af[mi],  blf[j]);
                    }
            }
        }

        // stage next chunk into the other buffer
        if (ck + 1 < nk) {
            unsigned* nstage = sm_u + ((ck + 1) & 1) * SM_STAGE_U32;
            g_store(nstage, tid, ra, rb);
            __syncthreads();
        }
    }

    // epilogue
#pragma unroll
    for (int mi = 0; mi < 2; mi++) {
        long gm = m0 + wmb + mi * 16 + group;
#pragma unroll
        for (int ni = 0; ni < 8; ni++) {
            int gc = n0 + wnb + ni * 8 + 2 * tig;
            float v0 = acc[mi][ni][0], v1 = acc[mi][ni][1];
            float v2 = acc[mi][ni][2], v3 = acc[mi][ni][3];
            if (bias) {
                float b0 = bias[gc], b1 = bias[gc + 1];
                v0 += b0; v1 += b1; v2 += b0; v3 += b1;
            }
            if (res) {
                float2 r0 = *(const float2*)(res + gm * Ncols + gc);
                float2 r1 = *(const float2*)(res + (gm + 8) * Ncols + gc);
                v0 += r0.x; v1 += r0.y; v2 += r1.x; v3 += r1.y;
            }
            if (relu) {
                v0 = fmaxf(v0, 0.f); v1 = fmaxf(v1, 0.f);
                v2 = fmaxf(v2, 0.f); v3 = fmaxf(v3, 0.f);
            }
            *(float2*)(C + gm * Ncols + gc)       = make_float2(v0, v1);
            *(float2*)(C + (gm + 8) * Ncols + gc) = make_float2(v2, v3);
        }
    }
}

// ---------------- self-attention: tensor-core S, FFMA O ----------------
// smem: sQ[128][132] (scaled Q, later V), sK[128][132], sPt[128][132] ([key][q])
__global__ __launch_bounds__(256) void sa_attn_kernel(
    const float* __restrict__ Q, const float* __restrict__ K, const float* __restrict__ V,
    const unsigned char* __restrict__ mask, float* __restrict__ O)
{
    extern __shared__ float sm[];
    float* sQ  = sm;
    float* sK  = sm + 128 * SST;
    float* sPt = sm + 2 * 128 * SST;
    __shared__ unsigned char smask[128];

    const int h = blockIdx.x, b = blockIdx.y;
    const int tid = threadIdx.x;
    const int warp = tid >> 5, lane = tid & 31;
    const int group = lane >> 2, tig = lane & 3;
    const float* Qp = Q + ((long)b * SEQN) * DMODEL + h * 128;
    const float* Kp = K + ((long)b * SEQN) * DMODEL + h * 128;
    const float* Vp = V + ((long)b * SEQN) * DMODEL + h * 128;
    const float invs = 0.0883883476483184f;  // 1/sqrt(128)

    if (tid < 128) smask[tid] = mask[(long)b * SEQN + tid];
    // load Q (scaled) and K, row-major
    for (int idx = tid; idx < 128 * 32; idx += 256) {
        int r = idx >> 5;
        int c = (idx & 31) << 2;
        float4 qv = *(const float4*)(Qp + (long)r * DMODEL + c);
        qv.x *= invs; qv.y *= invs; qv.z *= invs; qv.w *= invs;
        *(float4*)&sQ[r * SST + c] = qv;
        *(float4*)&sK[r * SST + c] = *(const float4*)(Kp + (long)r * DMODEL + c);
    }
    __syncthreads();

    // S = Qs · K^T  via 3xTF32 MMA; warps 4(m) x 2(n), warp tile 32x64
    {
        const int wm = warp & 3, wn = warp >> 5 ? 0 : (warp >> 2);  // warp>>2 in 0..1
        const int wmb = wm * 32, wnb = (warp >> 2) * 64;
        float acc[2][8][4];
#pragma unroll
        for (int mi = 0; mi < 2; mi++)
#pragma unroll
            for (int ni = 0; ni < 8; ni++)
#pragma unroll
                for (int q = 0; q < 4; q++) acc[mi][ni][q] = 0.f;
        (void)wn;

        for (int kb = 0; kb < 128; kb += 8) {
            unsigned af[2][4], alf[2][4];
#pragma unroll
            for (int mi = 0; mi < 2; mi++) {
                int r = wmb + mi * 16 + group;
                float f0 = sQ[r * SST + kb + tig];
                float f1 = sQ[(r + 8) * SST + kb + tig];
                float f2 = sQ[r * SST + kb + tig + 4];
                float f3 = sQ[(r + 8) * SST + kb + tig + 4];
                split_tf32(f0, af[mi][0], alf[mi][0]);
                split_tf32(f1, af[mi][1], alf[mi][1]);
                split_tf32(f2, af[mi][2], alf[mi][2]);
                split_tf32(f3, af[mi][3], alf[mi][3]);
            }
#pragma unroll
            for (int j = 0; j < 8; j++) {
                int col = wnb + j * 8 + group;
                unsigned bf[2], blf[2];
                float g0 = sK[col * SST + kb + tig];
                float g1 = sK[col * SST + kb + tig + 4];
                split_tf32(g0, bf[0], blf[0]);
                split_tf32(g1, bf[1], blf[1]);
#pragma unroll
                for (int mi = 0; mi < 2; mi++) {
                    mma_tf32(acc[mi][j], af[mi],  bf);
                    mma_tf32(acc[mi][j], alf[mi], bf);
                    mma_tf32(acc[mi][j], af[mi],  blf);
                }
            }
        }
        // scatter to sPt[key][q] (transposed store, conflict-free: bank = 8*tig+group+...)
#pragma unroll
        for (int mi = 0; mi < 2; mi++) {
            int gm0 = wmb + mi * 16 + group;
#pragma unroll
            for (int ni = 0; ni < 8; ni++) {
                int gc0 = wnb + ni * 8 + 2 * tig;
                sPt[gc0 * SST + gm0]           = acc[mi][ni][0];
                sPt[(gc0 + 1) * SST + gm0]     = acc[mi][ni][1];
                sPt[gc0 * SST + gm0 + 8]       = acc[mi][ni][2];
                sPt[(gc0 + 1) * SST + gm0 + 8] = acc[mi][ni][3];
            }
        }
    }
    __syncthreads();

    // load V (row-major) into sQ; softmax on sPt columns (per query row)
    for (int idx = tid; idx < 128 * 32; idx += 256) {
        int r = idx >> 5;
        int c = (idx & 31) << 2;
        *(float4*)&sQ[r * SST + c] = *(const float4*)(Vp + (long)r * DMODEL + c);
    }
    for (int r = warp; r < 128; r += 8) {     // r = query row
        float vv[4];
        float mx = -1e30f;
#pragma unroll
        for (int q = 0; q < 4; q++) {
            int c = lane + q * 32;            // key index
            float s = sPt[c * SST + r];
            if (smask[c]) s = -1e10f;
            vv[q] = s; mx = fmaxf(mx, s);
        }
#pragma unroll
        for (int o = 16; o > 0; o >>= 1) mx = fmaxf(mx, __shfl_xor_sync(0xffffffffu, mx, o));
        float sum = 0.f;
#pragma unroll
        for (int q = 0; q < 4; q++) { vv[q] = expf(vv[q] - mx); sum += vv[q]; }
#pragma unroll
        for (int o = 16; o > 0; o >>= 1) sum += __shfl_xor_sync(0xffffffffu, sum, o);
        float rs = 1.f / sum;
#pragma unroll
        for (int q = 0; q < 4; q++) sPt[(lane + q * 32) * SST + r] = vv[q] * rs;
    }
    __syncthreads();

    // O = P @ V  (FFMA register tiles; A = sPt[key][q], B = sQ=V[key][d])
    const int tx = tid & 15, ty = tid >> 4;
    float oc[8][8];
#pragma unroll
    for (int i = 0; i < 8; i++)
#pragma unroll
        for (int j = 0; j < 8; j++) oc[i][j] = 0.f;
    for (int k = 0; k < 128; k++) {
        float a[8], bb[8];
#pragma unroll
        for (int i = 0; i < 8; i++) a[i]  = sPt[k * SST + ty * 8 + i];
#pragma unroll
        for (int j = 0; j < 8; j++) bb[j] = sQ[k * SST + tx * 8 + j];
#pragma unroll
        for (int i = 0; i < 8; i++)
#pragma unroll
            for (int j = 0; j < 8; j++)
                oc[i][j] = fmaf(a[i], bb[j], oc[i][j]);
    }
    float* Op = O + ((long)b * SEQN) * DMODEL + h * 128;
#pragma unroll
    for (int i = 0; i < 8; i++) {
        *(float4*)(Op + (long)(ty * 8 + i) * DMODEL + tx * 8)     = make_float4(oc[i][0], oc[i][1], oc[i][2], oc[i][3]);
        *(float4*)(Op + (long)(ty * 8 + i) * DMODEL + tx * 8 + 4) = make_float4(oc[i][4], oc[i][5], oc[i][6], oc[i][7]);
    }
}

// ---------------- LayerNorm over 256, warp per row ----------------
__global__ __launch_bounds__(256) void ln_kernel(
    const float* __restrict__ X, const float* __restrict__ gw,
    const float* __restrict__ bw, float* __restrict__ Y)
{
    long row = (long)blockIdx.x * 8 + (threadIdx.x >> 5);
    int lane = threadIdx.x & 31;
    const float* xp = X + row * 256 + lane * 8;
    float4 a = *(const float4*)xp;
    float4 b = *(const float4*)(xp + 4);
    float s = a.x + a.y + a.z + a.w + b.x + b.y + b.z + b.w;
#pragma unroll
    for (int o = 16; o > 0; o >>= 1) s += __shfl_xor_sync(0xffffffffu, s, o);
    float mean = s * 0.00390625f;
    float q = 0.f;
    q += (a.x - mean) * (a.x - mean); q += (a.y - mean) * (a.y - mean);
    q += (a.z - mean) * (a.z - mean); q += (a.w - mean) * (a.w - mean);
    q += (b.x - mean) * (b.x - mean); q += (b.y - mean) * (b.y - mean);
    q += (b.z - mean) * (b.z - mean); q += (b.w - mean) * (b.w - mean);
#pragma unroll
    for (int o = 16; o > 0; o >>= 1) q += __shfl_xor_sync(0xffffffffu, q, o);
    float rstd = rsqrtf(q * 0.00390625f + 1e-5f);
    int c = lane * 8;
    float4 g0 = *(const float4*)(gw + c), g1 = *(const float4*)(gw + c + 4);
    float4 b0 = *(const float4*)(bw + c), b1 = *(const float4*)(bw + c + 4);
    float4 o0, o1;
    o0.x = (a.x - mean) * rstd * g0.x + b0.x;
    o0.y = (a.y - mean) * rstd * g0.y + b0.y;
    o0.z = (a.z - mean) * rstd * g0.z + b0.z;
    o0.w = (a.w - mean) * rstd * g0.w + b0.w;
    o1.x = (b.x - mean) * rstd * g1.x + b1.x;
    o1.y = (b.y - mean) * rstd * g1.y + b1.y;
    o1.z = (b.z - mean) * rstd * g1.z + b1.z;
    o1.w = (b.w - mean) * rstd * g1.w + b1.w;
    *(float4*)(Y + row * 256 + c)     = o0;
    *(float4*)(Y + row * 256 + c + 4) = o1;
}

// ---------------- cross-attention + fc + LN + output MLP ----------------
__global__ __launch_bounds__(256) void ca_kernel(
    const float* __restrict__ QH, const float* __restrict__ KH, const float* __restrict__ VH,
    const unsigned char* __restrict__ mask,
    const float* __restrict__ fcw, const float* __restrict__ fcb,
    const float* __restrict__ lng, const float* __restrict__ lnb,
    const float* __restrict__ src, const float* __restrict__ srct,
    const float* __restrict__ w1, const float* __restrict__ b1,
    const float* __restrict__ w2, const float* __restrict__ b2,
    float* __restrict__ out_vec, float* __restrict__ out_attn)
{
    const int b = blockIdx.x;
    const int tid = threadIdx.x;
    __shared__ float s_q[256], s_p[256], s_o[256], s_y[256], s_h[128], s_red[16];

    s_q[tid] = QH[(long)b * 256 + tid];
    __syncthreads();

    const int h = tid >> 7, k = tid & 127;
    const int lane = tid & 31, warp = tid >> 5;

    const float* krow = KH + ((long)b * 128 + k) * 256 + h * 128;
    float s = 0.f;
#pragma unroll 8
    for (int d = 0; d < 128; d += 4) {
        float4 kv = *(const float4*)(krow + d);
        s += s_q[h * 128 + d + 0] * kv.x + s_q[h * 128 + d + 1] * kv.y
           + s_q[h * 128 + d + 2] * kv.z + s_q[h * 128 + d + 3] * kv.w;
    }
    s *= 0.0883883476483184f;
    if (mask[(long)b * 128 + k]) s = -1e10f;

    float mx = s;
#pragma unroll
    for (int o = 16; o > 0; o >>= 1) mx = fmaxf(mx, __shfl_xor_sync(0xffffffffu, mx, o));
    if (lane == 0) s_red[warp] = mx;
    __syncthreads();
    mx = fmaxf(fmaxf(s_red[h * 4 + 0], s_red[h * 4 + 1]),
               fmaxf(s_red[h * 4 + 2], s_red[h * 4 + 3]));
    float e = expf(s - mx);
    float sum = e;
#pragma unroll
    for (int o = 16; o > 0; o >>= 1) sum += __shfl_xor_sync(0xffffffffu, sum, o);
    if (lane == 0) s_red[8 + warp] = sum;
    __syncthreads();
    sum = s_red[8 + h * 4 + 0] + s_red[8 + h * 4 + 1] + s_red[8 + h * 4 + 2] + s_red[8 + h * 4 + 3];
    float p = e / sum;
    s_p[tid] = p;
    out_attn[((long)h * BATCH + b) * 128 + k] = p;
    __syncthreads();

    const int d = tid & 127;
    float o = 0.f;
#pragma unroll 8
    for (int kk = 0; kk < 128; kk++)
        o += s_p[h * 128 + kk] * VH[((long)b * 128 + kk) * 256 + h * 128 + d];
    s_o[tid] = o;
    __syncthreads();

    float y = fcb[tid];
    for (int i = 0; i < 256; i++) y += s_o[i] * fcw[i * 256 + tid];
    y += (tid < 128) ? src[(long)b * 128 + tid] : srct[(long)b * 128 + tid - 128];

    float t = y;
#pragma unroll
    for (int ofs = 16; ofs > 0; ofs >>= 1) t += __shfl_xor_sync(0xffffffffu, t, ofs);
    if (lane == 0) s_red[warp] = t;
    __syncthreads();
    float mean = (s_red[0] + s_red[1] + s_red[2] + s_red[3] +
                  s_red[4] + s_red[5] + s_red[6] + s_red[7]) * 0.00390625f;
    float dv = y - mean;
    t = dv * dv;
#pragma unroll
    for (int ofs = 16; ofs > 0; ofs >>= 1) t += __shfl_xor_sync(0xffffffffu, t, ofs);
    if (lane == 0) s_red[8 + warp] = t;
    __syncthreads();
    float var = (s_red[8] + s_red[9] + s_red[10] + s_red[11] +
                 s_red[12] + s_red[13] + s_red[14] + s_red[15]) * 0.00390625f;
    float rstd = rsqrtf(var + 1e-5f);
    s_y[tid] = dv * rstd * lng[tid] + lnb[tid];
    __syncthreads();

    if (tid < 128) {
        float hh = b1[tid];
        for (int i = 0; i < 256; i++) hh += s_y[i] * w1[i * 128 + tid];
        for (int i = 0; i < 128; i++) hh += src[(long)b * 128 + i] * w1[(256 + i) * 128 + tid];
        s_h[tid] = fmaxf(hh, 0.f);
    }
    __syncthreads();
    if (tid < 128) {
        float oo = b2[tid];
        for (int i = 0; i < 128; i++) oo += s_h[i] * w2[i * 128 + tid];
        out_vec[(long)b * 128 + tid] = oo;
    }
}

// ---------------- host ----------------
static float* sym_addr(const void* s) {
    void* p = nullptr;
    cudaGetSymbolAddress(&p, s);
    return (float*)p;
}

extern "C" void kernel_launch(void* const* d_in, const int* in_sizes, int n_in,
                              void* d_out, int out_size)
{
    const float* src   = (const float*)d_in[0];
    const float* srct  = (const float*)d_in[1];
    const float* seq   = (const float*)d_in[2];
    const float* seqt  = (const float*)d_in[3];
    const void*  maskraw = d_in[4];

    const float *sa_wq, *sa_wk, *sa_wv, *sa_fcw, *sa_fcb, *sa_lng, *sa_lnb;
    const float *ms_w1, *ms_b1, *ms_w2, *ms_b2;
    const float *ca_wq, *ca_wk, *ca_wv, *ca_fcw, *ca_fcb, *ca_lng, *ca_lnb;
    const float *mg_w1, *mg_b1, *mg_w2, *mg_b2;

    bool dict_order = (in_sizes[10] == 98304);
    if (dict_order) {
        sa_wq  = (const float*)d_in[5];
        sa_wk  = (const float*)d_in[6];
        sa_wv  = (const float*)d_in[7];
        sa_fcw = (const float*)d_in[8];
        sa_fcb = (const float*)d_in[9];
        ms_w1  = (const float*)d_in[10];
        ms_b1  = (const float*)d_in[11];
        ms_w2  = (const float*)d_in[12];
        ms_b2  = (const float*)d_in[13];
        ca_wq  = (const float*)d_in[14];
        ca_wk  = (const float*)d_in[15];
        ca_wv  = (const float*)d_in[16];
        ca_fcw = (const float*)d_in[17];
        ca_fcb = (const float*)d_in[18];
        mg_w1  = (const float*)d_in[19];
        mg_b1  = (const float*)d_in[20];
        mg_w2  = (const float*)d_in[21];
        mg_b2  = (const float*)d_in[22];
        sa_lng = (const float*)d_in[23];
        sa_lnb = (const float*)d_in[24];
        ca_lng = (const float*)d_in[25];
        ca_lnb = (const float*)d_in[26];
    } else {
        sa_wq  = (const float*)d_in[5];
        sa_wk  = (const float*)d_in[6];
        sa_wv  = (const float*)d_in[7];
        sa_fcw = (const float*)d_in[8];
        sa_fcb = (const float*)d_in[9];
        sa_lng = (const float*)d_in[10];
        sa_lnb = (const float*)d_in[11];
        ms_w1  = (const float*)d_in[12];
        ms_b1  = (const float*)d_in[13];
        ms_w2  = (const float*)d_in[14];
        ms_b2  = (const float*)d_in[15];
        ca_wq  = (const float*)d_in[16];
        ca_wk  = (const float*)d_in[17];
        ca_wv  = (const float*)d_in[18];
        ca_fcw = (const float*)d_in[19];
        ca_fcb = (const float*)d_in[20];
        ca_lng = (const float*)d_in[21];
        ca_lnb = (const float*)d_in[22];
        mg_w1  = (const float*)d_in[23];
        mg_b1  = (const float*)d_in[24];
        mg_w2  = (const float*)d_in[25];
        mg_b2  = (const float*)d_in[26];
    }
    float* out = (float*)d_out;

    float* KV = sym_addr(g_KV);
    float* Qb = sym_addr(g_Q);
    float* Kb = sym_addr(g_K);
    float* Vb = sym_addr(g_V);
    float* AO = sym_addr(g_AO);
    float* FC = sym_addr(g_FC);
    float* SA = sym_addr(g_SA);
    float* H1 = sym_addr(g_H1);
    float* KC = sym_addr(g_KC);
    float* KH = sym_addr(g_KH);
    float* VH = sym_addr(g_VH);
    float* QH = sym_addr(g_QH);
    unsigned char* MK = (unsigned char*)sym_addr(g_mask8);

    const int SMEM_ATTN = 3 * 128 * SST * 4;       // 202752 bytes
    cudaFuncSetAttribute(sa_attn_kernel, cudaFuncAttributeMaxDynamicSharedMemorySize, SMEM_ATTN);
    const int SMEM_GEMM = 2 * SM_STAGE_U32 * 4;    // 143360 bytes
    cudaFuncSetAttribute(gemm_tc_kernel, cudaFuncAttributeMaxDynamicSharedMemorySize, SMEM_GEMM);

    detect_mask_kernel<<<1, 32>>>(maskraw);
    norm_mask_kernel<<<NROWS / 256, 256>>>(maskraw);

    concat_kv_kernel<<<ELEMS / 4 / 256, 256>>>(seq, seqt);

    dim3 g2(2, NROWS / 128);
    gemm_tc_kernel<<<g2, 256, SMEM_GEMM>>>(KV, 256, 256, nullptr, 0, sa_wq, 256, 256, nullptr, nullptr, 0, Qb);
    gemm_tc_kernel<<<g2, 256, SMEM_GEMM>>>(KV, 256, 256, nullptr, 0, sa_wk, 256, 256, nullptr, nullptr, 0, Kb);
    gemm_tc_kernel<<<g2, 256, SMEM_GEMM>>>(KV, 256, 256, nullptr, 0, sa_wv, 256, 256, nullptr, nullptr, 0, Vb);

    dim3 ga(2, BATCH);
    sa_attn_kernel<<<ga, 256, SMEM_ATTN>>>(Qb, Kb, Vb, MK, AO);

    gemm_tc_kernel<<<g2, 256, SMEM_GEMM>>>(AO, 256, 256, nullptr, 0, sa_fcw, 256, 256, sa_fcb, KV, 0, FC);
    ln_kernel<<<NROWS / 8, 256>>>(FC, sa_lng, sa_lnb, SA);

    gemm_tc_kernel<<<g2, 256, SMEM_GEMM>>>(SA, 256, 256, seq, 128, ms_w1, 384, 256, ms_b1, nullptr, 1, H1);
    gemm_tc_kernel<<<g2, 256, SMEM_GEMM>>>(H1, 256, 256, nullptr, 0, ms_w2, 256, 256, ms_b2, nullptr, 0, KC);

    gemm_tc_kernel<<<g2, 256, SMEM_GEMM>>>(KC, 256, 256, nullptr, 0, ca_wk, 256, 256, nullptr, nullptr, 0, KH);
    gemm_tc_kernel<<<g2, 256, SMEM_GEMM>>>(KC, 256, 256, nullptr, 0, ca_wv, 256, 256, nullptr, nullptr, 0, VH);

    dim3 gq(2, BATCH / 128);
    gemm_tc_kernel<<<gq, 256, SMEM_GEMM>>>(src, 128, 128, srct, 128, ca_wq, 256, 256, nullptr, nullptr, 0, QH);

    ca_kernel<<<BATCH, 256>>>(QH, KH, VH, MK,
                              ca_fcw, ca_fcb, ca_lng, ca_lnb,
                              src, srct, mg_w1, mg_b1, mg_w2, mg_b2,
                              out, out + (long)BATCH * 128);
}

// round 6
// speedup vs baseline: 1.4134x; 1.0187x over previous
#include <cuda_runtime.h>
#include <math.h>

#define BATCH  1024
#define SEQN   128
#define DMODEL 256
#define NROWS  (BATCH*SEQN)            // 131072
#define ELEMS  (BATCH*SEQN*DMODEL)     // 33554432
#define SST    132                     // padded smem row stride (floats)

// GEMM tensor-core tile config (single stage)
#define ASTR 36     // A smem row stride (u32)
#define BSTR 136    // B smem row stride (u32)
#define SM_AH 0
#define SM_AL (128*ASTR)
#define SM_BH (2*128*ASTR)
#define SM_BL (2*128*ASTR + 32*BSTR)
#define SM_STAGE_U32 (2*128*ASTR + 2*32*BSTR)   // 17920 u32 = 71680 B

// ---------------- scratch ----------------
__device__ float g_KV[ELEMS];
__device__ float g_Q [ELEMS];
__device__ float g_K [ELEMS];
__device__ float g_V [ELEMS];
__device__ float g_AO[ELEMS];
__device__ float g_FC[ELEMS];
__device__ float g_SA[ELEMS];
__device__ float g_H1[ELEMS];
__device__ float g_KC[ELEMS];
__device__ float g_KH[ELEMS];
__device__ float g_VH[ELEMS];
__device__ float g_QH[BATCH*DMODEL];
__device__ unsigned char g_mask8[NROWS];
__device__ int g_mask_mode;

// ---------------- mask dtype detection + normalization ----------------
__global__ void detect_mask_kernel(const void* mask) {
    if (threadIdx.x == 0 && blockIdx.x == 0) {
        const unsigned* p = (const unsigned*)mask;
        int mode = 1;
        for (int i = 0; i < 1024; i++) {
            unsigned v = p[i];
            if (v == 0x3F800000u) { mode = 2; break; }
            if (v > 1u) { mode = 0; break; }
        }
        g_mask_mode = mode;
    }
}

__global__ __launch_bounds__(256) void norm_mask_kernel(const void* mask) {
    int i = blockIdx.x * 256 + threadIdx.x;
    if (i >= NROWS) return;
    int mode = g_mask_mode;
    unsigned char m;
    if (mode == 0)      m = (((const unsigned char*)mask)[i] != 0);
    else if (mode == 1) m = (((const int*)mask)[i] != 0);
    else                m = (((const float*)mask)[i] != 0.f);
    g_mask8[i] = m;
}

// ---------------- concat([seq, seq_t], -1) -> KV ----------------
__global__ __launch_bounds__(256) void concat_kv_kernel(
    const float* __restrict__ seq, const float* __restrict__ seqt)
{
    long i4 = (long)blockIdx.x * 256 + threadIdx.x;
    if (i4 >= (long)ELEMS / 4) return;
    long row = i4 >> 6;
    int  c4  = (int)(i4 & 63);
    float4 v;
    if (c4 < 32) v = ((const float4*)(seq  + row * 128))[c4];
    else         v = ((const float4*)(seqt + row * 128))[c4 - 32];
    ((float4*)(g_KV + row * 256))[c4] = v;
}

// ---------------- tf32 helpers ----------------
__device__ __forceinline__ unsigned cvt_tf32(float x) {
    unsigned u;
    asm("cvt.rna.tf32.f32 %0, %1;" : "=r"(u) : "f"(x));
    return u;
}
__device__ __forceinline__ void split_tf32(float x, unsigned& hi, unsigned& lo) {
    hi = cvt_tf32(x);
    lo = cvt_tf32(x - __uint_as_float(hi));
}
__device__ __forceinline__ void mma_tf32(float* d, const unsigned* a, const unsigned* b) {
    asm volatile(
        "mma.sync.aligned.m16n8k8.row.col.f32.tf32.tf32.f32 "
        "{%0,%1,%2,%3}, {%4,%5,%6,%7}, {%8,%9}, {%0,%1,%2,%3};\n"
        : "+f"(d[0]), "+f"(d[1]), "+f"(d[2]), "+f"(d[3])
        : "r"(a[0]), "r"(a[1]), "r"(a[2]), "r"(a[3]),
          "r"(b[0]), "r"(b[1]));
}

// ---------------- 3xTF32 tensor-core GEMM, single stage, 2 CTAs/SM ----------------
__global__ __launch_bounds__(256, 2) void gemm_tc_kernel(
    const float* __restrict__ A1, int K1, int lda1,
    const float* __restrict__ A2, int lda2,
    const float* __restrict__ W, int Ktot, int Ncols,
    const float* __restrict__ bias,
    const float* __restrict__ res,
    int relu,
    float* __restrict__ C)
{
    extern __shared__ unsigned sm_u[];
    unsigned* sAh = sm_u + SM_AH;
    unsigned* sAl = sm_u + SM_AL;
    unsigned* sBh = sm_u + SM_BH;
    unsigned* sBl = sm_u + SM_BL;

    const int tid  = threadIdx.x;
    const int warp = tid >> 5, lane = tid & 31;
    const int wm = warp & 3, wn = warp >> 2;
    const int group = lane >> 2, tig = lane & 3;
    const long m0 = (long)blockIdx.y * 128;
    const int  n0 = blockIdx.x * 128;
    const int wmb = wm * 32;
    const int wnb = wn * 64;

    float acc[2][8][4];
#pragma unroll
    for (int mi = 0; mi < 2; mi++)
#pragma unroll
        for (int ni = 0; ni < 8; ni++)
#pragma unroll
            for (int q = 0; q < 4; q++) acc[mi][ni][q] = 0.f;

    const int nk = Ktot / 32;

    for (int ck = 0; ck < nk; ck++) {
        const int k0 = ck * 32;
        if (ck > 0) __syncthreads();   // MMA consumers of prev chunk done

        // load + split + store (A: 128x32, B: 32x128)
#pragma unroll
        for (int i = 0; i < 4; i++) {
            int f4 = tid + i * 256;
            int row = f4 >> 3, c = (f4 & 7) * 4;
            const float* ap = (k0 < K1) ? (A1 + (m0 + row) * (long)lda1 + k0 + c)
                                        : (A2 + (m0 + row) * (long)lda2 + (k0 - K1) + c);
            float4 v = *(const float4*)ap;
            uint4 h, l;
            split_tf32(v.x, h.x, l.x);
            split_tf32(v.y, h.y, l.y);
            split_tf32(v.z, h.z, l.z);
            split_tf32(v.w, h.w, l.w);
            *(uint4*)&sAh[row * ASTR + c] = h;
            *(uint4*)&sAl[row * ASTR + c] = l;
        }
#pragma unroll
        for (int i = 0; i < 4; i++) {
            int f4 = tid + i * 256;
            int row = f4 >> 5, c = (f4 & 31) * 4;
            float4 v = *(const float4*)(W + (long)(k0 + row) * Ncols + n0 + c);
            uint4 h, l;
            split_tf32(v.x, h.x, l.x);
            split_tf32(v.y, h.y, l.y);
            split_tf32(v.z, h.z, l.z);
            split_tf32(v.w, h.w, l.w);
            *(uint4*)&sBh[row * BSTR + c] = h;
            *(uint4*)&sBl[row * BSTR + c] = l;
        }
        __syncthreads();

#pragma unroll
        for (int ks = 0; ks < 4; ks++) {
            const int kb = ks * 8;
            unsigned af[2][4], alf[2][4];
#pragma unroll
            for (int mi = 0; mi < 2; mi++) {
                int r = wmb + mi * 16 + group;
                af[mi][0]  = sAh[r * ASTR + kb + tig];
                af[mi][1]  = sAh[(r + 8) * ASTR + kb + tig];
                af[mi][2]  = sAh[r * ASTR + kb + tig + 4];
                af[mi][3]  = sAh[(r + 8) * ASTR + kb + tig + 4];
                alf[mi][0] = sAl[r * ASTR + kb + tig];
                alf[mi][1] = sAl[(r + 8) * ASTR + kb + tig];
                alf[mi][2] = sAl[r * ASTR + kb + tig + 4];
                alf[mi][3] = sAl[(r + 8) * ASTR + kb + tig + 4];
            }
#pragma unroll
            for (int half = 0; half < 2; half++) {
                unsigned bf[4][2], blf[4][2];
#pragma unroll
                for (int j = 0; j < 4; j++) {
                    int col = wnb + (half * 4 + j) * 8 + group;
                    bf[j][0]  = sBh[(kb + tig) * BSTR + col];
                    bf[j][1]  = sBh[(kb + tig + 4) * BSTR + col];
                    blf[j][0] = sBl[(kb + tig) * BSTR + col];
                    blf[j][1] = sBl[(kb + tig + 4) * BSTR + col];
                }
#pragma unroll
                for (int mi = 0; mi < 2; mi++)
#pragma unroll
                    for (int j = 0; j < 4; j++) {
                        int ni = half * 4 + j;
                        mma_tf32(acc[mi][ni], af[mi],  bf[j]);
                        mma_tf32(acc[mi][ni], alf[mi], bf[j]);
                        mma_tf32(acc[mi][ni], af[mi],  blf[j]);
                    }
            }
        }
    }

    // epilogue
#pragma unroll
    for (int mi = 0; mi < 2; mi++) {
        long gm = m0 + wmb + mi * 16 + group;
#pragma unroll
        for (int ni = 0; ni < 8; ni++) {
            int gc = n0 + wnb + ni * 8 + 2 * tig;
            float v0 = acc[mi][ni][0], v1 = acc[mi][ni][1];
            float v2 = acc[mi][ni][2], v3 = acc[mi][ni][3];
            if (bias) {
                float b0 = bias[gc], b1 = bias[gc + 1];
                v0 += b0; v1 += b1; v2 += b0; v3 += b1;
            }
            if (res) {
                float2 r0 = *(const float2*)(res + gm * Ncols + gc);
                float2 r1 = *(const float2*)(res + (gm + 8) * Ncols + gc);
                v0 += r0.x; v1 += r0.y; v2 += r1.x; v3 += r1.y;
            }
            if (relu) {
                v0 = fmaxf(v0, 0.f); v1 = fmaxf(v1, 0.f);
                v2 = fmaxf(v2, 0.f); v3 = fmaxf(v3, 0.f);
            }
            *(float2*)(C + gm * Ncols + gc)       = make_float2(v0, v1);
            *(float2*)(C + (gm + 8) * Ncols + gc) = make_float2(v2, v3);
        }
    }
}

// ---------------- self-attention: tensor-core S, FFMA O ----------------
__global__ __launch_bounds__(256) void sa_attn_kernel(
    const float* __restrict__ Q, const float* __restrict__ K, const float* __restrict__ V,
    const unsigned char* __restrict__ mask, float* __restrict__ O)
{
    extern __shared__ float sm[];
    float* sQ  = sm;
    float* sK  = sm + 128 * SST;
    float* sPt = sm + 2 * 128 * SST;
    __shared__ unsigned char smask[128];

    const int h = blockIdx.x, b = blockIdx.y;
    const int tid = threadIdx.x;
    const int warp = tid >> 5, lane = tid & 31;
    const int group = lane >> 2, tig = lane & 3;
    const float* Qp = Q + ((long)b * SEQN) * DMODEL + h * 128;
    const float* Kp = K + ((long)b * SEQN) * DMODEL + h * 128;
    const float* Vp = V + ((long)b * SEQN) * DMODEL + h * 128;
    const float invs = 0.0883883476483184f;  // 1/sqrt(128)

    if (tid < 128) smask[tid] = mask[(long)b * SEQN + tid];
    for (int idx = tid; idx < 128 * 32; idx += 256) {
        int r = idx >> 5;
        int c = (idx & 31) << 2;
        float4 qv = *(const float4*)(Qp + (long)r * DMODEL + c);
        qv.x *= invs; qv.y *= invs; qv.z *= invs; qv.w *= invs;
        *(float4*)&sQ[r * SST + c] = qv;
        *(float4*)&sK[r * SST + c] = *(const float4*)(Kp + (long)r * DMODEL + c);
    }
    __syncthreads();

    // S = Qs · K^T via 3xTF32 MMA; warps 4(m) x 2(n), warp tile 32x64
    {
        const int wm = warp & 3;
        const int wmb = wm * 32, wnb = (warp >> 2) * 64;
        float acc[2][8][4];
#pragma unroll
        for (int mi = 0; mi < 2; mi++)
#pragma unroll
            for (int ni = 0; ni < 8; ni++)
#pragma unroll
                for (int q = 0; q < 4; q++) acc[mi][ni][q] = 0.f;

        for (int kb = 0; kb < 128; kb += 8) {
            unsigned af[2][4], alf[2][4];
#pragma unroll
            for (int mi = 0; mi < 2; mi++) {
                int r = wmb + mi * 16 + group;
                split_tf32(sQ[r * SST + kb + tig],           af[mi][0], alf[mi][0]);
                split_tf32(sQ[(r + 8) * SST + kb + tig],     af[mi][1], alf[mi][1]);
                split_tf32(sQ[r * SST + kb + tig + 4],       af[mi][2], alf[mi][2]);
                split_tf32(sQ[(r + 8) * SST + kb + tig + 4], af[mi][3], alf[mi][3]);
            }
#pragma unroll
            for (int j = 0; j < 8; j++) {
                int col = wnb + j * 8 + group;
                unsigned bf[2], blf[2];
                split_tf32(sK[col * SST + kb + tig],     bf[0], blf[0]);
                split_tf32(sK[col * SST + kb + tig + 4], bf[1], blf[1]);
#pragma unroll
                for (int mi = 0; mi < 2; mi++) {
                    mma_tf32(acc[mi][j], af[mi],  bf);
                    mma_tf32(acc[mi][j], alf[mi], bf);
                    mma_tf32(acc[mi][j], af[mi],  blf);
                }
            }
        }
#pragma unroll
        for (int mi = 0; mi < 2; mi++) {
            int gm0 = wmb + mi * 16 + group;
#pragma unroll
            for (int ni = 0; ni < 8; ni++) {
                int gc0 = wnb + ni * 8 + 2 * tig;
                sPt[gc0 * SST + gm0]           = acc[mi][ni][0];
                sPt[(gc0 + 1) * SST + gm0]     = acc[mi][ni][1];
                sPt[gc0 * SST + gm0 + 8]       = acc[mi][ni][2];
                sPt[(gc0 + 1) * SST + gm0 + 8] = acc[mi][ni][3];
            }
        }
    }
    __syncthreads();

    // load V into sQ; softmax on sPt columns (per query row)
    for (int idx = tid; idx < 128 * 32; idx += 256) {
        int r = idx >> 5;
        int c = (idx & 31) << 2;
        *(float4*)&sQ[r * SST + c] = *(const float4*)(Vp + (long)r * DMODEL + c);
    }
    for (int r = warp; r < 128; r += 8) {
        float vv[4];
        float mx = -1e30f;
#pragma unroll
        for (int q = 0; q < 4; q++) {
            int c = lane + q * 32;
            float s = sPt[c * SST + r];
            if (smask[c]) s = -1e10f;
            vv[q] = s; mx = fmaxf(mx, s);
        }
#pragma unroll
        for (int o = 16; o > 0; o >>= 1) mx = fmaxf(mx, __shfl_xor_sync(0xffffffffu, mx, o));
        float sum = 0.f;
#pragma unroll
        for (int q = 0; q < 4; q++) { vv[q] = expf(vv[q] - mx); sum += vv[q]; }
#pragma unroll
        for (int o = 16; o > 0; o >>= 1) sum += __shfl_xor_sync(0xffffffffu, sum, o);
        float rs = 1.f / sum;
#pragma unroll
        for (int q = 0; q < 4; q++) sPt[(lane + q * 32) * SST + r] = vv[q] * rs;
    }
    __syncthreads();

    // O = P @ V (FFMA register tiles)
    const int tx = tid & 15, ty = tid >> 4;
    float oc[8][8];
#pragma unroll
    for (int i = 0; i < 8; i++)
#pragma unroll
        for (int j = 0; j < 8; j++) oc[i][j] = 0.f;
    for (int k = 0; k < 128; k++) {
        float a[8], bb[8];
#pragma unroll
        for (int i = 0; i < 8; i++) a[i]  = sPt[k * SST + ty * 8 + i];
#pragma unroll
        for (int j = 0; j < 8; j++) bb[j] = sQ[k * SST + tx * 8 + j];
#pragma unroll
        for (int i = 0; i < 8; i++)
#pragma unroll
            for (int j = 0; j < 8; j++)
                oc[i][j] = fmaf(a[i], bb[j], oc[i][j]);
    }
    float* Op = O + ((long)b * SEQN) * DMODEL + h * 128;
#pragma unroll
    for (int i = 0; i < 8; i++) {
        *(float4*)(Op + (long)(ty * 8 + i) * DMODEL + tx * 8)     = make_float4(oc[i][0], oc[i][1], oc[i][2], oc[i][3]);
        *(float4*)(Op + (long)(ty * 8 + i) * DMODEL + tx * 8 + 4) = make_float4(oc[i][4], oc[i][5], oc[i][6], oc[i][7]);
    }
}

// ---------------- LayerNorm over 256, warp per row ----------------
__global__ __launch_bounds__(256) void ln_kernel(
    const float* __restrict__ X, const float* __restrict__ gw,
    const float* __restrict__ bw, float* __restrict__ Y)
{
    long row = (long)blockIdx.x * 8 + (threadIdx.x >> 5);
    int lane = threadIdx.x & 31;
    const float* xp = X + row * 256 + lane * 8;
    float4 a = *(const float4*)xp;
    float4 b = *(const float4*)(xp + 4);
    float s = a.x + a.y + a.z + a.w + b.x + b.y + b.z + b.w;
#pragma unroll
    for (int o = 16; o > 0; o >>= 1) s += __shfl_xor_sync(0xffffffffu, s, o);
    float mean = s * 0.00390625f;
    float q = 0.f;
    q += (a.x - mean) * (a.x - mean); q += (a.y - mean) * (a.y - mean);
    q += (a.z - mean) * (a.z - mean); q += (a.w - mean) * (a.w - mean);
    q += (b.x - mean) * (b.x - mean); q += (b.y - mean) * (b.y - mean);
    q += (b.z - mean) * (b.z - mean); q += (b.w - mean) * (b.w - mean);
#pragma unroll
    for (int o = 16; o > 0; o >>= 1) q += __shfl_xor_sync(0xffffffffu, q, o);
    float rstd = rsqrtf(q * 0.00390625f + 1e-5f);
    int c = lane * 8;
    float4 g0 = *(const float4*)(gw + c), g1 = *(const float4*)(gw + c + 4);
    float4 b0 = *(const float4*)(bw + c), b1 = *(const float4*)(bw + c + 4);
    float4 o0, o1;
    o0.x = (a.x - mean) * rstd * g0.x + b0.x;
    o0.y = (a.y - mean) * rstd * g0.y + b0.y;
    o0.z = (a.z - mean) * rstd * g0.z + b0.z;
    o0.w = (a.w - mean) * rstd * g0.w + b0.w;
    o1.x = (b.x - mean) * rstd * g1.x + b1.x;
    o1.y = (b.y - mean) * rstd * g1.y + b1.y;
    o1.z = (b.z - mean) * rstd * g1.z + b1.z;
    o1.w = (b.w - mean) * rstd * g1.w + b1.w;
    *(float4*)(Y + row * 256 + c)     = o0;
    *(float4*)(Y + row * 256 + c + 4) = o1;
}

// ---------------- cross-attention + fc + LN + output MLP ----------------
__global__ __launch_bounds__(256) void ca_kernel(
    const float* __restrict__ QH, const float* __restrict__ KH, const float* __restrict__ VH,
    const unsigned char* __restrict__ mask,
    const float* __restrict__ fcw, const float* __restrict__ fcb,
    const float* __restrict__ lng, const float* __restrict__ lnb,
    const float* __restrict__ src, const float* __restrict__ srct,
    const float* __restrict__ w1, const float* __restrict__ b1,
    const float* __restrict__ w2, const float* __restrict__ b2,
    float* __restrict__ out_vec, float* __restrict__ out_attn)
{
    const int b = blockIdx.x;
    const int tid = threadIdx.x;
    __shared__ float s_q[256], s_p[256], s_o[256], s_y[256], s_h[128], s_red[16];

    s_q[tid] = QH[(long)b * 256 + tid];
    __syncthreads();

    const int h = tid >> 7, k = tid & 127;
    const int lane = tid & 31, warp = tid >> 5;

    const float* krow = KH + ((long)b * 128 + k) * 256 + h * 128;
    float s = 0.f;
#pragma unroll 8
    for (int d = 0; d < 128; d += 4) {
        float4 kv = *(const float4*)(krow + d);
        s += s_q[h * 128 + d + 0] * kv.x + s_q[h * 128 + d + 1] * kv.y
           + s_q[h * 128 + d + 2] * kv.z + s_q[h * 128 + d + 3] * kv.w;
    }
    s *= 0.0883883476483184f;
    if (mask[(long)b * 128 + k]) s = -1e10f;

    float mx = s;
#pragma unroll
    for (int o = 16; o > 0; o >>= 1) mx = fmaxf(mx, __shfl_xor_sync(0xffffffffu, mx, o));
    if (lane == 0) s_red[warp] = mx;
    __syncthreads();
    mx = fmaxf(fmaxf(s_red[h * 4 + 0], s_red[h * 4 + 1]),
               fmaxf(s_red[h * 4 + 2], s_red[h * 4 + 3]));
    float e = expf(s - mx);
    float sum = e;
#pragma unroll
    for (int o = 16; o > 0; o >>= 1) sum += __shfl_xor_sync(0xffffffffu, sum, o);
    if (lane == 0) s_red[8 + warp] = sum;
    __syncthreads();
    sum = s_red[8 + h * 4 + 0] + s_red[8 + h * 4 + 1] + s_red[8 + h * 4 + 2] + s_red[8 + h * 4 + 3];
    float p = e / sum;
    s_p[tid] = p;
    out_attn[((long)h * BATCH + b) * 128 + k] = p;
    __syncthreads();

    const int d = tid & 127;
    float o = 0.f;
#pragma unroll 8
    for (int kk = 0; kk < 128; kk++)
        o += s_p[h * 128 + kk] * VH[((long)b * 128 + kk) * 256 + h * 128 + d];
    s_o[tid] = o;
    __syncthreads();

    float y = fcb[tid];
    for (int i = 0; i < 256; i++) y += s_o[i] * fcw[i * 256 + tid];
    y += (tid < 128) ? src[(long)b * 128 + tid] : srct[(long)b * 128 + tid - 128];

    float t = y;
#pragma unroll
    for (int ofs = 16; ofs > 0; ofs >>= 1) t += __shfl_xor_sync(0xffffffffu, t, ofs);
    if (lane == 0) s_red[warp] = t;
    __syncthreads();
    float mean = (s_red[0] + s_red[1] + s_red[2] + s_red[3] +
                  s_red[4] + s_red[5] + s_red[6] + s_red[7]) * 0.00390625f;
    float dv = y - mean;
    t = dv * dv;
#pragma unroll
    for (int ofs = 16; ofs > 0; ofs >>= 1) t += __shfl_xor_sync(0xffffffffu, t, ofs);
    if (lane == 0) s_red[8 + warp] = t;
    __syncthreads();
    float var = (s_red[8] + s_red[9] + s_red[10] + s_red[11] +
                 s_red[12] + s_red[13] + s_red[14] + s_red[15]) * 0.00390625f;
    float rstd = rsqrtf(var + 1e-5f);
    s_y[tid] = dv * rstd * lng[tid] + lnb[tid];
    __syncthreads();

    if (tid < 128) {
        float hh = b1[tid];
        for (int i = 0; i < 256; i++) hh += s_y[i] * w1[i * 128 + tid];
        for (int i = 0; i < 128; i++) hh += src[(long)b * 128 + i] * w1[(256 + i) * 128 + tid];
        s_h[tid] = fmaxf(hh, 0.f);
    }
    __syncthreads();
    if (tid < 128) {
        float oo = b2[tid];
        for (int i = 0; i < 128; i++) oo += s_h[i] * w2[i * 128 + tid];
        out_vec[(long)b * 128 + tid] = oo;
    }
}

// ---------------- host ----------------
static float* sym_addr(const void* s) {
    void* p = nullptr;
    cudaGetSymbolAddress(&p, s);
    return (float*)p;
}

extern "C" void kernel_launch(void* const* d_in, const int* in_sizes, int n_in,
                              void* d_out, int out_size)
{
    const float* src   = (const float*)d_in[0];
    const float* srct  = (const float*)d_in[1];
    const float* seq   = (const float*)d_in[2];
    const float* seqt  = (const float*)d_in[3];
    const void*  maskraw = d_in[4];

    const float *sa_wq, *sa_wk, *sa_wv, *sa_fcw, *sa_fcb, *sa_lng, *sa_lnb;
    const float *ms_w1, *ms_b1, *ms_w2, *ms_b2;
    const float *ca_wq, *ca_wk, *ca_wv, *ca_fcw, *ca_fcb, *ca_lng, *ca_lnb;
    const float *mg_w1, *mg_b1, *mg_w2, *mg_b2;

    bool dict_order = (in_sizes[10] == 98304);
    if (dict_order) {
        sa_wq  = (const float*)d_in[5];
        sa_wk  = (const float*)d_in[6];
        sa_wv  = (const float*)d_in[7];
        sa_fcw = (const float*)d_in[8];
        sa_fcb = (const float*)d_in[9];
        ms_w1  = (const float*)d_in[10];
        ms_b1  = (const float*)d_in[11];
        ms_w2  = (const float*)d_in[12];
        ms_b2  = (const float*)d_in[13];
        ca_wq  = (const float*)d_in[14];
        ca_wk  = (const float*)d_in[15];
        ca_wv  = (const float*)d_in[16];
        ca_fcw = (const float*)d_in[17];
        ca_fcb = (const float*)d_in[18];
        mg_w1  = (const float*)d_in[19];
        mg_b1  = (const float*)d_in[20];
        mg_w2  = (const float*)d_in[21];
        mg_b2  = (const float*)d_in[22];
        sa_lng = (const float*)d_in[23];
        sa_lnb = (const float*)d_in[24];
        ca_lng = (const float*)d_in[25];
        ca_lnb = (const float*)d_in[26];
    } else {
        sa_wq  = (const float*)d_in[5];
        sa_wk  = (const float*)d_in[6];
        sa_wv  = (const float*)d_in[7];
        sa_fcw = (const float*)d_in[8];
        sa_fcb = (const float*)d_in[9];
        sa_lng = (const float*)d_in[10];
        sa_lnb = (const float*)d_in[11];
        ms_w1  = (const float*)d_in[12];
        ms_b1  = (const float*)d_in[13];
        ms_w2  = (const float*)d_in[14];
        ms_b2  = (const float*)d_in[15];
        ca_wq  = (const float*)d_in[16];
        ca_wk  = (const float*)d_in[17];
        ca_wv  = (const float*)d_in[18];
        ca_fcw = (const float*)d_in[19];
        ca_fcb = (const float*)d_in[20];
        ca_lng = (const float*)d_in[21];
        ca_lnb = (const float*)d_in[22];
        mg_w1  = (const float*)d_in[23];
        mg_b1  = (const float*)d_in[24];
        mg_w2  = (const float*)d_in[25];
        mg_b2  = (const float*)d_in[26];
    }
    float* out = (float*)d_out;

    float* KV = sym_addr(g_KV);
    float* Qb = sym_addr(g_Q);
    float* Kb = sym_addr(g_K);
    float* Vb = sym_addr(g_V);
    float* AO = sym_addr(g_AO);
    float* FC = sym_addr(g_FC);
    float* SA = sym_addr(g_SA);
    float* H1 = sym_addr(g_H1);
    float* KC = sym_addr(g_KC);
    float* KH = sym_addr(g_KH);
    float* VH = sym_addr(g_VH);
    float* QH = sym_addr(g_QH);
    unsigned char* MK = (unsigned char*)sym_addr(g_mask8);

    const int SMEM_ATTN = 3 * 128 * SST * 4;   // 202752 bytes
    cudaFuncSetAttribute(sa_attn_kernel, cudaFuncAttributeMaxDynamicSharedMemorySize, SMEM_ATTN);
    const int SMEM_GEMM = SM_STAGE_U32 * 4;    // 71680 bytes (2 CTAs/SM)
    cudaFuncSetAttribute(gemm_tc_kernel, cudaFuncAttributeMaxDynamicSharedMemorySize, SMEM_GEMM);

    detect_mask_kernel<<<1, 32>>>(maskraw);
    norm_mask_kernel<<<NROWS / 256, 256>>>(maskraw);

    concat_kv_kernel<<<ELEMS / 4 / 256, 256>>>(seq, seqt);

    dim3 g2(2, NROWS / 128);
    gemm_tc_kernel<<<g2, 256, SMEM_GEMM>>>(KV, 256, 256, nullptr, 0, sa_wq, 256, 256, nullptr, nullptr, 0, Qb);
    gemm_tc_kernel<<<g2, 256, SMEM_GEMM>>>(KV, 256, 256, nullptr, 0, sa_wk, 256, 256, nullptr, nullptr, 0, Kb);
    gemm_tc_kernel<<<g2, 256, SMEM_GEMM>>>(KV, 256, 256, nullptr, 0, sa_wv, 256, 256, nullptr, nullptr, 0, Vb);

    dim3 ga(2, BATCH);
    sa_attn_kernel<<<ga, 256, SMEM_ATTN>>>(Qb, Kb, Vb, MK, AO);

    gemm_tc_kernel<<<g2, 256, SMEM_GEMM>>>(AO, 256, 256, nullptr, 0, sa_fcw, 256, 256, sa_fcb, KV, 0, FC);
    ln_kernel<<<NROWS / 8, 256>>>(FC, sa_lng, sa_lnb, SA);

    gemm_tc_kernel<<<g2, 256, SMEM_GEMM>>>(SA, 256, 256, seq, 128, ms_w1, 384, 256, ms_b1, nullptr, 1, H1);
    gemm_tc_kernel<<<g2, 256, SMEM_GEMM>>>(H1, 256, 256, nullptr, 0, ms_w2, 256, 256, ms_b2, nullptr, 0, KC);

    gemm_tc_kernel<<<g2, 256, SMEM_GEMM>>>(KC, 256, 256, nullptr, 0, ca_wk, 256, 256, nullptr, nullptr, 0, KH);
    gemm_tc_kernel<<<g2, 256, SMEM_GEMM>>>(KC, 256, 256, nullptr, 0, ca_wv, 256, 256, nullptr, nullptr, 0, VH);

    dim3 gq(2, BATCH / 128);
    gemm_tc_kernel<<<gq, 256, SMEM_GEMM>>>(src, 128, 128, srct, 128, ca_wq, 256, 256, nullptr, nullptr, 0, QH);

    ca_kernel<<<BATCH, 256>>>(QH, KH, VH, MK,
                              ca_fcw, ca_fcb, ca_lng, ca_lnb,
                              src, srct, mg_w1, mg_b1, mg_w2, mg_b2,
                              out, out + (long)BATCH * 128);
}

// round 8
// speedup vs baseline: 1.9834x; 1.4034x over previous
#include <cuda_runtime.h>
#include <cuda_bf16.h>
#include <math.h>

#define BATCH  1024
#define SEQN   128
#define DMODEL 256
#define NROWS  (BATCH*SEQN)            // 131072
#define ELEMS  (BATCH*SEQN*DMODEL)     // 33554432
#define SST    132                     // padded smem row stride (floats)

// bf16 GEMM smem layout, u32 units. Row stride = 20 u32 (32 bf16 + pad) = 80 B.
#define RSTR 20
#define UA_H 0                       // A hi: 128 rows
#define UA_L (128*RSTR)              // A lo
#define UB_H (2*128*RSTR)            // B hi: 128 n-rows (transposed [n][k])
#define UB_L (2*128*RSTR + 128*RSTR) // B lo
#define SM_GEMM_U32 (4*128*RSTR)     // 10240 u32 = 40960 B

// ---------------- scratch ----------------
__device__ float g_KV[ELEMS];
__device__ float g_Q [ELEMS];
__device__ float g_K [ELEMS];
__device__ float g_V [ELEMS];
__device__ float g_AO[ELEMS];
__device__ float g_FC[ELEMS];
__device__ float g_SA[ELEMS];
__device__ float g_H1[ELEMS];
__device__ float g_KC[ELEMS];
__device__ float g_KH[ELEMS];
__device__ float g_VH[ELEMS];
__device__ float g_QH[BATCH*DMODEL];
__device__ unsigned char g_mask8[NROWS];
__device__ int g_mask_mode;

// ---------------- mask dtype detection + normalization ----------------
__global__ void detect_mask_kernel(const void* mask) {
    if (threadIdx.x == 0 && blockIdx.x == 0) {
        const unsigned* p = (const unsigned*)mask;
        int mode = 1;
        for (int i = 0; i < 1024; i++) {
            unsigned v = p[i];
            if (v == 0x3F800000u) { mode = 2; break; }
            if (v > 1u) { mode = 0; break; }
        }
        g_mask_mode = mode;
    }
}

__global__ __launch_bounds__(256) void norm_mask_kernel(const void* mask) {
    int i = blockIdx.x * 256 + threadIdx.x;
    if (i >= NROWS) return;
    int mode = g_mask_mode;
    unsigned char m;
    if (mode == 0)      m = (((const unsigned char*)mask)[i] != 0);
    else if (mode == 1) m = (((const int*)mask)[i] != 0);
    else                m = (((const float*)mask)[i] != 0.f);
    g_mask8[i] = m;
}

// ---------------- concat([seq, seq_t], -1) -> KV ----------------
__global__ __launch_bounds__(256) void concat_kv_kernel(
    const float* __restrict__ seq, const float* __restrict__ seqt)
{
    long i4 = (long)blockIdx.x * 256 + threadIdx.x;
    if (i4 >= (long)ELEMS / 4) return;
    long row = i4 >> 6;
    int  c4  = (int)(i4 & 63);
    float4 v;
    if (c4 < 32) v = ((const float4*)(seq  + row * 128))[c4];
    else         v = ((const float4*)(seqt + row * 128))[c4 - 32];
    ((float4*)(g_KV + row * 256))[c4] = v;
}

// ---------------- tf32 helpers (sa_attn) ----------------
__device__ __forceinline__ unsigned cvt_tf32(float x) {
    unsigned u;
    asm("cvt.rna.tf32.f32 %0, %1;" : "=r"(u) : "f"(x));
    return u;
}
__device__ __forceinline__ void split_tf32(float x, unsigned& hi, unsigned& lo) {
    hi = cvt_tf32(x);
    lo = cvt_tf32(x - __uint_as_float(hi));
}
__device__ __forceinline__ void mma_tf32(float* d, const unsigned* a, const unsigned* b) {
    asm volatile(
        "mma.sync.aligned.m16n8k8.row.col.f32.tf32.tf32.f32 "
        "{%0,%1,%2,%3}, {%4,%5,%6,%7}, {%8,%9}, {%0,%1,%2,%3};\n"
        : "+f"(d[0]), "+f"(d[1]), "+f"(d[2]), "+f"(d[3])
        : "r"(a[0]), "r"(a[1]), "r"(a[2]), "r"(a[3]),
          "r"(b[0]), "r"(b[1]));
}

// ---------------- bf16 helpers ----------------
// returns packed u32: lower 16 bits = bf16(lo), upper = bf16(hi)
__device__ __forceinline__ unsigned pack_bf16x2(float lo, float hi) {
    unsigned r;
    asm("cvt.rn.bf16x2.f32 %0, %1, %2;" : "=r"(r) : "f"(hi), "f"(lo));
    return r;
}
__device__ __forceinline__ float lo_bf16f(unsigned u) { return __uint_as_float(u << 16); }
__device__ __forceinline__ float hi_bf16f(unsigned u) { return __uint_as_float(u & 0xFFFF0000u); }

__device__ __forceinline__ void mma_bf16(float* d, const unsigned* a, const unsigned* b) {
    asm volatile(
        "mma.sync.aligned.m16n8k16.row.col.f32.bf16.bf16.f32 "
        "{%0,%1,%2,%3}, {%4,%5,%6,%7}, {%8,%9}, {%0,%1,%2,%3};\n"
        : "+f"(d[0]), "+f"(d[1]), "+f"(d[2]), "+f"(d[3])
        : "r"(a[0]), "r"(a[1]), "r"(a[2]), "r"(a[3]),
          "r"(b[0]), "r"(b[1]));
}

// ---------------- 3xBF16 tensor-core GEMM (m16n8k16, direct fragment LDS) ----------------
// C[M,N] = concat(A1,A2)[M,Ktot] @ W[Ktot,N] (+bias)(+res)(relu)
// BM=128, BN=128, BK=32; 256 thr; warps 4(m)x2(n); warp tile 32x64.
// smem: A hi/lo as [m][k] packed-pairs, B hi/lo TRANSPOSED as [n][k] packed-pairs.
__global__ __launch_bounds__(256, 2) void gemm_tc_kernel(
    const float* __restrict__ A1, int K1, int lda1,
    const float* __restrict__ A2, int lda2,
    const float* __restrict__ W, int Ktot, int Ncols,
    const float* __restrict__ bias,
    const float* __restrict__ res,
    int relu,
    float* __restrict__ C)
{
    extern __shared__ unsigned su[];
    unsigned* sAh = su + UA_H;
    unsigned* sAl = su + UA_L;
    unsigned* sBh = su + UB_H;
    unsigned* sBl = su + UB_L;

    const int tid  = threadIdx.x;
    const int warp = tid >> 5, lane = tid & 31;
    const int wm = warp & 3, wn = warp >> 2;
    const int group = lane >> 2, tig = lane & 3;
    const long m0 = (long)blockIdx.y * 128;
    const int  n0 = blockIdx.x * 128;
    const int wmb = wm * 32;
    const int wnb = wn * 64;

    float acc[2][8][4];
#pragma unroll
    for (int mi = 0; mi < 2; mi++)
#pragma unroll
        for (int ni = 0; ni < 8; ni++)
#pragma unroll
            for (int q = 0; q < 4; q++) acc[mi][ni][q] = 0.f;

    const int nk = Ktot / 32;

    for (int ck = 0; ck < nk; ck++) {
        const int k0 = ck * 32;
        if (ck > 0) __syncthreads();

        // ---- stage A (128 m x 32 k), [m][k] packed pairs ----
#pragma unroll
        for (int i = 0; i < 4; i++) {
            int f4 = tid + i * 256;
            int row = f4 >> 3, c = (f4 & 7) * 4;     // c: k offset (float idx)
            const float* ap = (k0 < K1) ? (A1 + (m0 + row) * (long)lda1 + k0 + c)
                                        : (A2 + (m0 + row) * (long)lda2 + (k0 - K1) + c);
            float4 v = *(const float4*)ap;
            unsigned h0 = pack_bf16x2(v.x, v.y);     // lower = k=c (even)
            unsigned h1 = pack_bf16x2(v.z, v.w);
            float r0 = v.x - lo_bf16f(h0), r1 = v.y - hi_bf16f(h0);
            float r2 = v.z - lo_bf16f(h1), r3 = v.w - hi_bf16f(h1);
            unsigned l0 = pack_bf16x2(r0, r1);
            unsigned l1 = pack_bf16x2(r2, r3);
            int ui = row * RSTR + (c >> 1);          // u32 index (c/2 even -> uint2 ok)
            *(uint2*)&sAh[ui] = make_uint2(h0, h1);
            *(uint2*)&sAl[ui] = make_uint2(l0, l1);
        }
        // ---- stage B (32 k x 128 n) TRANSPOSED to [n][k] packed k-pairs ----
        // thread handles one (k-quad, n): loads W[k0+kq*4 + j][n0+n], j=0..3
#pragma unroll
        for (int i = 0; i < 4; i++) {
            int task = tid + i * 256;                // 0..1023
            int n  = task & 127;
            int kq = task >> 7;                      // 0..7
            const float* wp = W + (long)(k0 + kq * 4) * Ncols + n0 + n;
            float f0 = wp[0];
            float f1 = wp[Ncols];
            float f2 = wp[2 * Ncols];
            float f3 = wp[3 * Ncols];
            unsigned h0 = pack_bf16x2(f0, f1);       // lower = k even
            unsigned h1 = pack_bf16x2(f2, f3);
            float r0 = f0 - lo_bf16f(h0), r1 = f1 - hi_bf16f(h0);
            float r2 = f2 - lo_bf16f(h1), r3 = f3 - hi_bf16f(h1);
            unsigned l0 = pack_bf16x2(r0, r1);
            unsigned l1 = pack_bf16x2(r2, r3);
            int ui = n * RSTR + kq * 2;              // even -> uint2 ok
            *(uint2*)&sBh[ui] = make_uint2(h0, h1);
            *(uint2*)&sBl[ui] = make_uint2(l0, l1);
        }
        __syncthreads();

        // ---- compute: 2 k-steps of k=16 ----
#pragma unroll
        for (int ks = 0; ks < 2; ks++) {
            const int kb8 = ks * 8;                  // u32 offset of this k16 step
            unsigned ah[2][4], al[2][4];
#pragma unroll
            for (int mi = 0; mi < 2; mi++) {
                int r = wmb + mi * 16 + group;
                int i0 = r * RSTR + kb8 + tig;       // a0: row r,  k pair 2*tig
                int i1 = (r + 8) * RSTR + kb8 + tig; // a1: row r+8
                ah[mi][0] = sAh[i0];
                ah[mi][1] = sAh[i1];
                ah[mi][2] = sAh[i0 + 4];             // a2: k+8
                ah[mi][3] = sAh[i1 + 4];
                al[mi][0] = sAl[i0];
                al[mi][1] = sAl[i1];
                al[mi][2] = sAl[i0 + 4];
                al[mi][3] = sAl[i1 + 4];
            }
#pragma unroll
            for (int nt = 0; nt < 8; nt++) {
                int nrow = wnb + nt * 8 + group;
                int bi = nrow * RSTR + kb8 + tig;
                unsigned bh[2], bl[2];
                bh[0] = sBh[bi];                     // b0: k pair 2*tig
                bh[1] = sBh[bi + 4];                 // b1: k+8
                bl[0] = sBl[bi];
                bl[1] = sBl[bi + 4];
#pragma unroll
                for (int mi = 0; mi < 2; mi++) {
                    mma_bf16(acc[mi][nt], ah[mi], bh);
                    mma_bf16(acc[mi][nt], al[mi], bh);
                    mma_bf16(acc[mi][nt], ah[mi], bl);
                }
            }
        }
    }

    // epilogue (same c-fragment layout as tf32 version)
#pragma unroll
    for (int mi = 0; mi < 2; mi++) {
        long gm = m0 + wmb + mi * 16 + group;
#pragma unroll
        for (int ni = 0; ni < 8; ni++) {
            int gc = n0 + wnb + ni * 8 + 2 * tig;
            float v0 = acc[mi][ni][0], v1 = acc[mi][ni][1];
            float v2 = acc[mi][ni][2], v3 = acc[mi][ni][3];
            if (bias) {
                float b0 = bias[gc], b1 = bias[gc + 1];
                v0 += b0; v1 += b1; v2 += b0; v3 += b1;
            }
            if (res) {
                float2 r0 = *(const float2*)(res + gm * Ncols + gc);
                float2 r1 = *(const float2*)(res + (gm + 8) * Ncols + gc);
                v0 += r0.x; v1 += r0.y; v2 += r1.x; v3 += r1.y;
            }
            if (relu) {
                v0 = fmaxf(v0, 0.f); v1 = fmaxf(v1, 0.f);
                v2 = fmaxf(v2, 0.f); v3 = fmaxf(v3, 0.f);
            }
            *(float2*)(C + gm * Ncols + gc)       = make_float2(v0, v1);
            *(float2*)(C + (gm + 8) * Ncols + gc) = make_float2(v2, v3);
        }
    }
}

// ---------------- self-attention: tensor-core S (tf32), FFMA O ----------------
__global__ __launch_bounds__(256) void sa_attn_kernel(
    const float* __restrict__ Q, const float* __restrict__ K, const float* __restrict__ V,
    const unsigned char* __restrict__ mask, float* __restrict__ O)
{
    extern __shared__ float sm[];
    float* sQ  = sm;
    float* sK  = sm + 128 * SST;
    float* sPt = sm + 2 * 128 * SST;
    __shared__ unsigned char smask[128];

    const int h = blockIdx.x, b = blockIdx.y;
    const int tid = threadIdx.x;
    const int warp = tid >> 5, lane = tid & 31;
    const int group = lane >> 2, tig = lane & 3;
    const float* Qp = Q + ((long)b * SEQN) * DMODEL + h * 128;
    const float* Kp = K + ((long)b * SEQN) * DMODEL + h * 128;
    const float* Vp = V + ((long)b * SEQN) * DMODEL + h * 128;
    const float invs = 0.0883883476483184f;

    if (tid < 128) smask[tid] = mask[(long)b * SEQN + tid];
    for (int idx = tid; idx < 128 * 32; idx += 256) {
        int r = idx >> 5;
        int c = (idx & 31) << 2;
        float4 qv = *(const float4*)(Qp + (long)r * DMODEL + c);
        qv.x *= invs; qv.y *= invs; qv.z *= invs; qv.w *= invs;
        *(float4*)&sQ[r * SST + c] = qv;
        *(float4*)&sK[r * SST + c] = *(const float4*)(Kp + (long)r * DMODEL + c);
    }
    __syncthreads();

    {
        const int wm = warp & 3;
        const int wmb = wm * 32, wnb = (warp >> 2) * 64;
        float acc[2][8][4];
#pragma unroll
        for (int mi = 0; mi < 2; mi++)
#pragma unroll
            for (int ni = 0; ni < 8; ni++)
#pragma unroll
                for (int q = 0; q < 4; q++) acc[mi][ni][q] = 0.f;

        for (int kb = 0; kb < 128; kb += 8) {
            unsigned af[2][4], alf[2][4];
#pragma unroll
            for (int mi = 0; mi < 2; mi++) {
                int r = wmb + mi * 16 + group;
                split_tf32(sQ[r * SST + kb + tig],           af[mi][0], alf[mi][0]);
                split_tf32(sQ[(r + 8) * SST + kb + tig],     af[mi][1], alf[mi][1]);
                split_tf32(sQ[r * SST + kb + tig + 4],       af[mi][2], alf[mi][2]);
                split_tf32(sQ[(r + 8) * SST + kb + tig + 4], af[mi][3], alf[mi][3]);
            }
#pragma unroll
            for (int j = 0; j < 8; j++) {
                int col = wnb + j * 8 + group;
                unsigned bf[2], blf[2];
                split_tf32(sK[col * SST + kb + tig],     bf[0], blf[0]);
                split_tf32(sK[col * SST + kb + tig + 4], bf[1], blf[1]);
#pragma unroll
                for (int mi = 0; mi < 2; mi++) {
                    mma_tf32(acc[mi][j], af[mi],  bf);
                    mma_tf32(acc[mi][j], alf[mi], bf);
                    mma_tf32(acc[mi][j], af[mi],  blf);
                }
            }
        }
#pragma unroll
        for (int mi = 0; mi < 2; mi++) {
            int gm0 = wmb + mi * 16 + group;
#pragma unroll
            for (int ni = 0; ni < 8; ni++) {
                int gc0 = wnb + ni * 8 + 2 * tig;
                sPt[gc0 * SST + gm0]           = acc[mi][ni][0];
                sPt[(gc0 + 1) * SST + gm0]     = acc[mi][ni][1];
                sPt[gc0 * SST + gm0 + 8]       = acc[mi][ni][2];
                sPt[(gc0 + 1) * SST + gm0 + 8] = acc[mi][ni][3];
            }
        }
    }
    __syncthreads();

    for (int idx = tid; idx < 128 * 32; idx += 256) {
        int r = idx >> 5;
        int c = (idx & 31) << 2;
        *(float4*)&sQ[r * SST + c] = *(const float4*)(Vp + (long)r * DMODEL + c);
    }
    for (int r = warp; r < 128; r += 8) {
        float vv[4];
        float mx = -1e30f;
#pragma unroll
        for (int q = 0; q < 4; q++) {
            int c = lane + q * 32;
            float s = sPt[c * SST + r];
            if (smask[c]) s = -1e10f;
            vv[q] = s; mx = fmaxf(mx, s);
        }
#pragma unroll
        for (int o = 16; o > 0; o >>= 1) mx = fmaxf(mx, __shfl_xor_sync(0xffffffffu, mx, o));
        float sum = 0.f;
#pragma unroll
        for (int q = 0; q < 4; q++) { vv[q] = expf(vv[q] - mx); sum += vv[q]; }
#pragma unroll
        for (int o = 16; o > 0; o >>= 1) sum += __shfl_xor_sync(0xffffffffu, sum, o);
        float rs = 1.f / sum;
#pragma unroll
        for (int q = 0; q < 4; q++) sPt[(lane + q * 32) * SST + r] = vv[q] * rs;
    }
    __syncthreads();

    const int tx = tid & 15, ty = tid >> 4;
    float oc[8][8];
#pragma unroll
    for (int i = 0; i < 8; i++)
#pragma unroll
        for (int j = 0; j < 8; j++) oc[i][j] = 0.f;
    for (int k = 0; k < 128; k++) {
        float a[8], bb[8];
#pragma unroll
        for (int i = 0; i < 8; i++) a[i]  = sPt[k * SST + ty * 8 + i];
#pragma unroll
        for (int j = 0; j < 8; j++) bb[j] = sQ[k * SST + tx * 8 + j];
#pragma unroll
        for (int i = 0; i < 8; i++)
#pragma unroll
            for (int j = 0; j < 8; j++)
                oc[i][j] = fmaf(a[i], bb[j], oc[i][j]);
    }
    float* Op = O + ((long)b * SEQN) * DMODEL + h * 128;
#pragma unroll
    for (int i = 0; i < 8; i++) {
        *(float4*)(Op + (long)(ty * 8 + i) * DMODEL + tx * 8)     = make_float4(oc[i][0], oc[i][1], oc[i][2], oc[i][3]);
        *(float4*)(Op + (long)(ty * 8 + i) * DMODEL + tx * 8 + 4) = make_float4(oc[i][4], oc[i][5], oc[i][6], oc[i][7]);
    }
}

// ---------------- LayerNorm over 256, warp per row ----------------
__global__ __launch_bounds__(256) void ln_kernel(
    const float* __restrict__ X, const float* __restrict__ gw,
    const float* __restrict__ bw, float* __restrict__ Y)
{
    long row = (long)blockIdx.x * 8 + (threadIdx.x >> 5);
    int lane = threadIdx.x & 31;
    const float* xp = X + row * 256 + lane * 8;
    float4 a = *(const float4*)xp;
    float4 b = *(const float4*)(xp + 4);
    float s = a.x + a.y + a.z + a.w + b.x + b.y + b.z + b.w;
#pragma unroll
    for (int o = 16; o > 0; o >>= 1) s += __shfl_xor_sync(0xffffffffu, s, o);
    float mean = s * 0.00390625f;
    float q = 0.f;
    q += (a.x - mean) * (a.x - mean); q += (a.y - mean) * (a.y - mean);
    q += (a.z - mean) * (a.z - mean); q += (a.w - mean) * (a.w - mean);
    q += (b.x - mean) * (b.x - mean); q += (b.y - mean) * (b.y - mean);
    q += (b.z - mean) * (b.z - mean); q += (b.w - mean) * (b.w - mean);
#pragma unroll
    for (int o = 16; o > 0; o >>= 1) q += __shfl_xor_sync(0xffffffffu, q, o);
    float rstd = rsqrtf(q * 0.00390625f + 1e-5f);
    int c = lane * 8;
    float4 g0 = *(const float4*)(gw + c), g1 = *(const float4*)(gw + c + 4);
    float4 b0 = *(const float4*)(bw + c), b1 = *(const float4*)(bw + c + 4);
    float4 o0, o1;
    o0.x = (a.x - mean) * rstd * g0.x + b0.x;
    o0.y = (a.y - mean) * rstd * g0.y + b0.y;
    o0.z = (a.z - mean) * rstd * g0.z + b0.z;
    o0.w = (a.w - mean) * rstd * g0.w + b0.w;
    o1.x = (b.x - mean) * rstd * g1.x + b1.x;
    o1.y = (b.y - mean) * rstd * g1.y + b1.y;
    o1.z = (b.z - mean) * rstd * g1.z + b1.z;
    o1.w = (b.w - mean) * rstd * g1.w + b1.w;
    *(float4*)(Y + row * 256 + c)     = o0;
    *(float4*)(Y + row * 256 + c + 4) = o1;
}

// ---------------- cross-attention + fc + LN + output MLP ----------------
__global__ __launch_bounds__(256) void ca_kernel(
    const float* __restrict__ QH, const float* __restrict__ KH, const float* __restrict__ VH,
    const unsigned char* __restrict__ mask,
    const float* __restrict__ fcw, const float* __restrict__ fcb,
    const float* __restrict__ lng, const float* __restrict__ lnb,
    const float* __restrict__ src, const float* __restrict__ srct,
    const float* __restrict__ w1, const float* __restrict__ b1,
    const float* __restrict__ w2, const float* __restrict__ b2,
    float* __restrict__ out_vec, float* __restrict__ out_attn)
{
    const int b = blockIdx.x;
    const int tid = threadIdx.x;
    __shared__ float s_q[256], s_p[256], s_o[256], s_y[256], s_h[128], s_red[16];

    s_q[tid] = QH[(long)b * 256 + tid];
    __syncthreads();

    const int h = tid >> 7, k = tid & 127;
    const int lane = tid & 31, warp = tid >> 5;

    const float* krow = KH + ((long)b * 128 + k) * 256 + h * 128;
    float s = 0.f;
#pragma unroll 8
    for (int d = 0; d < 128; d += 4) {
        float4 kv = *(const float4*)(krow + d);
        s += s_q[h * 128 + d + 0] * kv.x + s_q[h * 128 + d + 1] * kv.y
           + s_q[h * 128 + d + 2] * kv.z + s_q[h * 128 + d + 3] * kv.w;
    }
    s *= 0.0883883476483184f;
    if (mask[(long)b * 128 + k]) s = -1e10f;

    float mx = s;
#pragma unroll
    for (int o = 16; o > 0; o >>= 1) mx = fmaxf(mx, __shfl_xor_sync(0xffffffffu, mx, o));
    if (lane == 0) s_red[warp] = mx;
    __syncthreads();
    mx = fmaxf(fmaxf(s_red[h * 4 + 0], s_red[h * 4 + 1]),
               fmaxf(s_red[h * 4 + 2], s_red[h * 4 + 3]));
    float e = expf(s - mx);
    float sum = e;
#pragma unroll
    for (int o = 16; o > 0; o >>= 1) sum += __shfl_xor_sync(0xffffffffu, sum, o);
    if (lane == 0) s_red[8 + warp] = sum;
    __syncthreads();
    sum = s_red[8 + h * 4 + 0] + s_red[8 + h * 4 + 1] + s_red[8 + h * 4 + 2] + s_red[8 + h * 4 + 3];
    float p = e / sum;
    s_p[tid] = p;
    out_attn[((long)h * BATCH + b) * 128 + k] = p;
    __syncthreads();

    const int d = tid & 127;
    float o = 0.f;
#pragma unroll 8
    for (int kk = 0; kk < 128; kk++)
        o += s_p[h * 128 + kk] * VH[((long)b * 128 + kk) * 256 + h * 128 + d];
    s_o[tid] = o;
    __syncthreads();

    float y = fcb[tid];
    for (int i = 0; i < 256; i++) y += s_o[i] * fcw[i * 256 + tid];
    y += (tid < 128) ? src[(long)b * 128 + tid] : srct[(long)b * 128 + tid - 128];

    float t = y;
#pragma unroll
    for (int ofs = 16; ofs > 0; ofs >>= 1) t += __shfl_xor_sync(0xffffffffu, t, ofs);
    if (lane == 0) s_red[warp] = t;
    __syncthreads();
    float mean = (s_red[0] + s_red[1] + s_red[2] + s_red[3] +
                  s_red[4] + s_red[5] + s_red[6] + s_red[7]) * 0.00390625f;
    float dv = y - mean;
    t = dv * dv;
#pragma unroll
    for (int ofs = 16; ofs > 0; ofs >>= 1) t += __shfl_xor_sync(0xffffffffu, t, ofs);
    if (lane == 0) s_red[8 + warp] = t;
    __syncthreads();
    float var = (s_red[8] + s_red[9] + s_red[10] + s_red[11] +
                 s_red[12] + s_red[13] + s_red[14] + s_red[15]) * 0.00390625f;
    float rstd = rsqrtf(var + 1e-5f);
    s_y[tid] = dv * rstd * lng[tid] + lnb[tid];
    __syncthreads();

    if (tid < 128) {
        float hh = b1[tid];
        for (int i = 0; i < 256; i++) hh += s_y[i] * w1[i * 128 + tid];
        for (int i = 0; i < 128; i++) hh += src[(long)b * 128 + i] * w1[(256 + i) * 128 + tid];
        s_h[tid] = fmaxf(hh, 0.f);
    }
    __syncthreads();
    if (tid < 128) {
        float oo = b2[tid];
        for (int i = 0; i < 128; i++) oo += s_h[i] * w2[i * 128 + tid];
        out_vec[(long)b * 128 + tid] = oo;
    }
}

// ---------------- host ----------------
static float* sym_addr(const void* s) {
    void* p = nullptr;
    cudaGetSymbolAddress(&p, s);
    return (float*)p;
}

extern "C" void kernel_launch(void* const* d_in, const int* in_sizes, int n_in,
                              void* d_out, int out_size)
{
    const float* src   = (const float*)d_in[0];
    const float* srct  = (const float*)d_in[1];
    const float* seq   = (const float*)d_in[2];
    const float* seqt  = (const float*)d_in[3];
    const void*  maskraw = d_in[4];

    const float *sa_wq, *sa_wk, *sa_wv, *sa_fcw, *sa_fcb, *sa_lng, *sa_lnb;
    const float *ms_w1, *ms_b1, *ms_w2, *ms_b2;
    const float *ca_wq, *ca_wk, *ca_wv, *ca_fcw, *ca_fcb, *ca_lng, *ca_lnb;
    const float *mg_w1, *mg_b1, *mg_w2, *mg_b2;

    bool dict_order = (in_sizes[10] == 98304);
    if (dict_order) {
        sa_wq  = (const float*)d_in[5];
        sa_wk  = (const float*)d_in[6];
        sa_wv  = (const float*)d_in[7];
        sa_fcw = (const float*)d_in[8];
        sa_fcb = (const float*)d_in[9];
        ms_w1  = (const float*)d_in[10];
        ms_b1  = (const float*)d_in[11];
        ms_w2  = (const float*)d_in[12];
        ms_b2  = (const float*)d_in[13];
        ca_wq  = (const float*)d_in[14];
        ca_wk  = (const float*)d_in[15];
        ca_wv  = (const float*)d_in[16];
        ca_fcw = (const float*)d_in[17];
        ca_fcb = (const float*)d_in[18];
        mg_w1  = (const float*)d_in[19];
        mg_b1  = (const float*)d_in[20];
        mg_w2  = (const float*)d_in[21];
        mg_b2  = (const float*)d_in[22];
        sa_lng = (const float*)d_in[23];
        sa_lnb = (const float*)d_in[24];
        ca_lng = (const float*)d_in[25];
        ca_lnb = (const float*)d_in[26];
    } else {
        sa_wq  = (const float*)d_in[5];
        sa_wk  = (const float*)d_in[6];
        sa_wv  = (const float*)d_in[7];
        sa_fcw = (const float*)d_in[8];
        sa_fcb = (const float*)d_in[9];
        sa_lng = (const float*)d_in[10];
        sa_lnb = (const float*)d_in[11];
        ms_w1  = (const float*)d_in[12];
        ms_b1  = (const float*)d_in[13];
        ms_w2  = (const float*)d_in[14];
        ms_b2  = (const float*)d_in[15];
        ca_wq  = (const float*)d_in[16];
        ca_wk  = (const float*)d_in[17];
        ca_wv  = (const float*)d_in[18];
        ca_fcw = (const float*)d_in[19];
        ca_fcb = (const float*)d_in[20];
        ca_lng = (const float*)d_in[21];
        ca_lnb = (const float*)d_in[22];
        mg_w1  = (const float*)d_in[23];
        mg_b1  = (const float*)d_in[24];
        mg_w2  = (const float*)d_in[25];
        mg_b2  = (const float*)d_in[26];
    }
    float* out = (float*)d_out;

    float* KV = sym_addr(g_KV);
    float* Qb = sym_addr(g_Q);
    float* Kb = sym_addr(g_K);
    float* Vb = sym_addr(g_V);
    float* AO = sym_addr(g_AO);
    float* FC = sym_addr(g_FC);
    float* SA = sym_addr(g_SA);
    float* H1 = sym_addr(g_H1);
    float* KC = sym_addr(g_KC);
    float* KH = sym_addr(g_KH);
    float* VH = sym_addr(g_VH);
    float* QH = sym_addr(g_QH);
    unsigned char* MK = (unsigned char*)sym_addr(g_mask8);

    const int SMEM_ATTN = 3 * 128 * SST * 4;   // 202752 bytes
    cudaFuncSetAttribute(sa_attn_kernel, cudaFuncAttributeMaxDynamicSharedMemorySize, SMEM_ATTN);
    const int SMEM_GEMM = SM_GEMM_U32 * 4;     // 40960 bytes (2 CTAs/SM)
    cudaFuncSetAttribute(gemm_tc_kernel, cudaFuncAttributeMaxDynamicSharedMemorySize, SMEM_GEMM);

    detect_mask_kernel<<<1, 32>>>(maskraw);
    norm_mask_kernel<<<NROWS / 256, 256>>>(maskraw);

    concat_kv_kernel<<<ELEMS / 4 / 256, 256>>>(seq, seqt);

    dim3 g2(2, NROWS / 128);
    gemm_tc_kernel<<<g2, 256, SMEM_GEMM>>>(KV, 256, 256, nullptr, 0, sa_wq, 256, 256, nullptr, nullptr, 0, Qb);
    gemm_tc_kernel<<<g2, 256, SMEM_GEMM>>>(KV, 256, 256, nullptr, 0, sa_wk, 256, 256, nullptr, nullptr, 0, Kb);
    gemm_tc_kernel<<<g2, 256, SMEM_GEMM>>>(KV, 256, 256, nullptr, 0, sa_wv, 256, 256, nullptr, nullptr, 0, Vb);

    dim3 ga(2, BATCH);
    sa_attn_kernel<<<ga, 256, SMEM_ATTN>>>(Qb, Kb, Vb, MK, AO);

    gemm_tc_kernel<<<g2, 256, SMEM_GEMM>>>(AO, 256, 256, nullptr, 0, sa_fcw, 256, 256, sa_fcb, KV, 0, FC);
    ln_kernel<<<NROWS / 8, 256>>>(FC, sa_lng, sa_lnb, SA);

    gemm_tc_kernel<<<g2, 256, SMEM_GEMM>>>(SA, 256, 256, seq, 128, ms_w1, 384, 256, ms_b1, nullptr, 1, H1);
    gemm_tc_kernel<<<g2, 256, SMEM_GEMM>>>(H1, 256, 256, nullptr, 0, ms_w2, 256, 256, ms_b2, nullptr, 0, KC);

    gemm_tc_kernel<<<g2, 256, SMEM_GEMM>>>(KC, 256, 256, nullptr, 0, ca_wk, 256, 256, nullptr, nullptr, 0, KH);
    gemm_tc_kernel<<<g2, 256, SMEM_GEMM>>>(KC, 256, 256, nullptr, 0, ca_wv, 256, 256, nullptr, nullptr, 0, VH);

    dim3 gq(2, BATCH / 128);
    gemm_tc_kernel<<<gq, 256, SMEM_GEMM>>>(src, 128, 128, srct, 128, ca_wq, 256, 256, nullptr, nullptr, 0, QH);

    ca_kernel<<<BATCH, 256>>>(QH, KH, VH, MK,
                              ca_fcw, ca_fcb, ca_lng, ca_lnb,
                              src, srct, mg_w1, mg_b1, mg_w2, mg_b2,
                              out, out + (long)BATCH * 128);
}